// round 1
// baseline (speedup 1.0000x reference)
#include <cuda_runtime.h>
#include <math.h>

#define BB 4
#define SS 2048
#define DD 1024
#define HH 16
#define HD 64

// Scratch (device globals; no allocations allowed)
__device__ float g_Q[(size_t)BB * HH * SS * HD];   // [B,H,S,64]
__device__ float g_K[(size_t)BB * HH * SS * HD];
__device__ float g_V[(size_t)BB * HH * SS * HD];
__device__ float g_AO[(size_t)BB * SS * DD];       // [B,S,H*64]

// ---------------------------------------------------------------------------
// Projection: Out[b,h,s,n] = sum_d A[b,s,d] * W[h,d,n]
// GEMM per head: M=B*S=8192, N=64, K=1024. Block = 64 rows x full head (64).
// 256 threads, each computes 4x4. k-tile = 16.
// ---------------------------------------------------------------------------
__global__ __launch_bounds__(256) void proj_kernel(const float* __restrict__ A,
                                                   const float* __restrict__ W,
                                                   float* __restrict__ Out) {
    __shared__ float As[16][68];  // [k][m] (A transposed)
    __shared__ float Ws[16][68];  // [k][n]

    const int m0 = blockIdx.x * 64;
    const int h  = blockIdx.y;
    const int tid = threadIdx.x;
    const int tx = tid & 15, ty = tid >> 4;
    const int r0 = ty * 4, c0 = tx * 4;

    // loaders
    const int ls  = tid >> 2;         // 0..63 : A row within tile
    const int ld4 = (tid & 3) * 4;    // 0..12 : k offset
    const int wk  = tid >> 4;         // 0..15 : W k-row
    const int wn4 = (tid & 15) * 4;   // 0..60 : W n offset

    const float* Arow = A + (size_t)(m0 + ls) * DD + ld4;
    const float* Wp   = W + (size_t)h * DD * HD + (size_t)wk * HD + wn4;

    float acc[4][4];
#pragma unroll
    for (int i = 0; i < 4; i++)
#pragma unroll
        for (int j = 0; j < 4; j++) acc[i][j] = 0.f;

    for (int k0 = 0; k0 < DD; k0 += 16) {
        float4 av = *(const float4*)(Arow + k0);
        float4 wv = *(const float4*)(Wp + (size_t)k0 * HD);
        __syncthreads();
        As[ld4 + 0][ls] = av.x; As[ld4 + 1][ls] = av.y;
        As[ld4 + 2][ls] = av.z; As[ld4 + 3][ls] = av.w;
        *(float4*)&Ws[wk][wn4] = wv;
        __syncthreads();
#pragma unroll
        for (int kk = 0; kk < 16; kk++) {
            float4 a4 = *(float4*)&As[kk][r0];
            float4 b4 = *(float4*)&Ws[kk][c0];
            float a[4] = {a4.x, a4.y, a4.z, a4.w};
            float b[4] = {b4.x, b4.y, b4.z, b4.w};
#pragma unroll
            for (int i = 0; i < 4; i++)
#pragma unroll
                for (int j = 0; j < 4; j++)
                    acc[i][j] = fmaf(a[i], b[j], acc[i][j]);
        }
    }

#pragma unroll
    for (int i = 0; i < 4; i++) {
        int m = m0 + r0 + i;
        int b = m / SS, s = m % SS;
        float4 v = make_float4(acc[i][0], acc[i][1], acc[i][2], acc[i][3]);
        *(float4*)&Out[(((size_t)b * HH + h) * SS + s) * HD + c0] = v;
    }
}

// ---------------------------------------------------------------------------
// Causal flash attention, fp32.
// Q,K,V: [B,H,S,64]; AO: [B,S,H*64].
// Block: one 64-row q-tile for one (b,h). 256 threads, 4x4 tiles.
// Dynamic smem: QsT[64][68] (d-major), KsT[64][68] (d-major, reused for P
// k-major), Vs[64][68] (row-major).
// ---------------------------------------------------------------------------
__global__ __launch_bounds__(256) void flash_kernel(const float* __restrict__ Q,
                                                    const float* __restrict__ K,
                                                    const float* __restrict__ V,
                                                    float* __restrict__ AO) {
    extern __shared__ float sm[];
    float* QsT = sm;                 // [d][r]
    float* KsT = sm + 64 * 68;       // [d][c]  -> later PsT [k][r]
    float* Vs  = sm + 2 * 64 * 68;   // [k][c]

    const int qi  = (int)gridDim.x - 1 - (int)blockIdx.x;  // heavy tiles first
    const int bh  = blockIdx.y;
    const int b   = bh >> 4, h = bh & 15;
    const int qm0 = qi * 64;

    const float* Qh = Q + (size_t)bh * SS * HD;
    const float* Kh = K + (size_t)bh * SS * HD;
    const float* Vh = V + (size_t)bh * SS * HD;

    const int tid = threadIdx.x;
    const int tx = tid & 15, ty = tid >> 4;
    const int r0 = ty * 4, c0 = tx * 4;
    const int ls = tid >> 2;
    const int ld4 = (tid & 3) * 4;

    // Load Q tile (transposed to d-major)
    {
        const float* qp = Qh + (size_t)(qm0 + ls) * HD + ld4;
#pragma unroll
        for (int it = 0; it < 4; it++) {
            float4 v4 = *(const float4*)(qp + it * 16);
            int d = ld4 + it * 16;
            QsT[(d + 0) * 68 + ls] = v4.x;
            QsT[(d + 1) * 68 + ls] = v4.y;
            QsT[(d + 2) * 68 + ls] = v4.z;
            QsT[(d + 3) * 68 + ls] = v4.w;
        }
    }

    float m_[4], l_[4], o[4][4];
#pragma unroll
    for (int i = 0; i < 4; i++) {
        m_[i] = -1e30f; l_[i] = 0.f;
#pragma unroll
        for (int j = 0; j < 4; j++) o[i][j] = 0.f;
    }

    for (int kt = 0; kt <= qi; kt++) {
        const int kn0 = kt * 64;
        __syncthreads();   // previous P·V done; Q visible on first iter
        {
            const float* kp = Kh + (size_t)(kn0 + ls) * HD + ld4;
            const float* vp = Vh + (size_t)(kn0 + ls) * HD + ld4;
#pragma unroll
            for (int it = 0; it < 4; it++) {
                float4 kv = *(const float4*)(kp + it * 16);
                int d = ld4 + it * 16;
                KsT[(d + 0) * 68 + ls] = kv.x;
                KsT[(d + 1) * 68 + ls] = kv.y;
                KsT[(d + 2) * 68 + ls] = kv.z;
                KsT[(d + 3) * 68 + ls] = kv.w;
                float4 vv = *(const float4*)(vp + it * 16);
                *(float4*)&Vs[ls * 68 + d] = vv;
            }
        }
        __syncthreads();

        // S = Q @ K^T  (4x4 per thread)
        float s4[4][4];
#pragma unroll
        for (int i = 0; i < 4; i++)
#pragma unroll
            for (int j = 0; j < 4; j++) s4[i][j] = 0.f;

        for (int d = 0; d < 64; d++) {
            float4 qa = *(float4*)&QsT[d * 68 + r0];
            float4 kb = *(float4*)&KsT[d * 68 + c0];
            float a[4] = {qa.x, qa.y, qa.z, qa.w};
            float c[4] = {kb.x, kb.y, kb.z, kb.w};
#pragma unroll
            for (int i = 0; i < 4; i++)
#pragma unroll
                for (int j = 0; j < 4; j++)
                    s4[i][j] = fmaf(a[i], c[j], s4[i][j]);
        }

        // scale + causal mask (only the diagonal tile needs masking)
        const float scale = 0.125f;  // 1/sqrt(64)
        if (kt == qi) {
#pragma unroll
            for (int i = 0; i < 4; i++)
#pragma unroll
                for (int j = 0; j < 4; j++)
                    s4[i][j] = (c0 + j > r0 + i) ? -1e30f : s4[i][j] * scale;
        } else {
#pragma unroll
            for (int i = 0; i < 4; i++)
#pragma unroll
                for (int j = 0; j < 4; j++) s4[i][j] *= scale;
        }

        // online softmax; row stats reduced across the 16 tx lanes
#pragma unroll
        for (int i = 0; i < 4; i++) {
            float mx = fmaxf(fmaxf(s4[i][0], s4[i][1]), fmaxf(s4[i][2], s4[i][3]));
#pragma unroll
            for (int off = 1; off < 16; off <<= 1)
                mx = fmaxf(mx, __shfl_xor_sync(0xffffffffu, mx, off));
            float mn = fmaxf(m_[i], mx);
            float alpha = __expf(m_[i] - mn);
            m_[i] = mn;
            float rs = 0.f;
#pragma unroll
            for (int j = 0; j < 4; j++) {
                float p = __expf(s4[i][j] - mn);
                s4[i][j] = p;
                rs += p;
            }
#pragma unroll
            for (int off = 1; off < 16; off <<= 1)
                rs += __shfl_xor_sync(0xffffffffu, rs, off);
            l_[i] = l_[i] * alpha + rs;
#pragma unroll
            for (int j = 0; j < 4; j++) o[i][j] *= alpha;
        }

        __syncthreads();  // all KsT reads done before overwriting with P
        // store P (k-major) into KsT buffer: PsT[k][r]
#pragma unroll
        for (int i = 0; i < 4; i++)
#pragma unroll
            for (int j = 0; j < 4; j++)
                KsT[(c0 + j) * 68 + (r0 + i)] = s4[i][j];
        __syncthreads();

        // O += P @ V
        for (int k = 0; k < 64; k++) {
            float4 pr = *(float4*)&KsT[k * 68 + r0];
            float4 vv = *(float4*)&Vs[k * 68 + c0];
            float p[4] = {pr.x, pr.y, pr.z, pr.w};
            float v4[4] = {vv.x, vv.y, vv.z, vv.w};
#pragma unroll
            for (int i = 0; i < 4; i++)
#pragma unroll
                for (int j = 0; j < 4; j++)
                    o[i][j] = fmaf(p[i], v4[j], o[i][j]);
        }
    }

    // epilogue: normalize and write to AO[b, s, h*64 + c]
#pragma unroll
    for (int i = 0; i < 4; i++) {
        float inv = 1.f / l_[i];
        float4 v = make_float4(o[i][0] * inv, o[i][1] * inv, o[i][2] * inv, o[i][3] * inv);
        size_t s = (size_t)qm0 + r0 + i;
        *(float4*)&AO[((size_t)b * SS + s) * DD + h * HD + c0] = v;
    }
}

// ---------------------------------------------------------------------------
// Output projection: Y[m,n] = sum_k AO[m,k] * Wo[n,k] + bo[n]
// M=8192, N=1024, K=1024. 64x64 tiles, 4x4 per thread, k-tile 16.
// ---------------------------------------------------------------------------
__global__ __launch_bounds__(256) void outproj_kernel(const float* __restrict__ A,
                                                      const float* __restrict__ Wo,
                                                      const float* __restrict__ bo,
                                                      float* __restrict__ Y) {
    __shared__ float As[16][68];  // [k][m]
    __shared__ float Bs[16][68];  // [k][n]

    const int m0 = blockIdx.x * 64;
    const int n0 = blockIdx.y * 64;
    const int tid = threadIdx.x;
    const int tx = tid & 15, ty = tid >> 4;
    const int r0 = ty * 4, c0 = tx * 4;
    const int ls = tid >> 2;
    const int ld4 = (tid & 3) * 4;

    const float* Ap = A  + (size_t)(m0 + ls) * DD + ld4;
    const float* Wp = Wo + (size_t)(n0 + ls) * DD + ld4;

    float acc[4][4];
#pragma unroll
    for (int i = 0; i < 4; i++)
#pragma unroll
        for (int j = 0; j < 4; j++) acc[i][j] = 0.f;

    for (int k0 = 0; k0 < DD; k0 += 16) {
        float4 av = *(const float4*)(Ap + k0);
        float4 wv = *(const float4*)(Wp + k0);
        __syncthreads();
        As[ld4 + 0][ls] = av.x; As[ld4 + 1][ls] = av.y;
        As[ld4 + 2][ls] = av.z; As[ld4 + 3][ls] = av.w;
        Bs[ld4 + 0][ls] = wv.x; Bs[ld4 + 1][ls] = wv.y;
        Bs[ld4 + 2][ls] = wv.z; Bs[ld4 + 3][ls] = wv.w;
        __syncthreads();
#pragma unroll
        for (int kk = 0; kk < 16; kk++) {
            float4 a4 = *(float4*)&As[kk][r0];
            float4 b4 = *(float4*)&Bs[kk][c0];
            float a[4] = {a4.x, a4.y, a4.z, a4.w};
            float b[4] = {b4.x, b4.y, b4.z, b4.w};
#pragma unroll
            for (int i = 0; i < 4; i++)
#pragma unroll
                for (int j = 0; j < 4; j++)
                    acc[i][j] = fmaf(a[i], b[j], acc[i][j]);
        }
    }

    float4 bb = *(const float4*)&bo[n0 + c0];
#pragma unroll
    for (int i = 0; i < 4; i++) {
        float4 v = make_float4(acc[i][0] + bb.x, acc[i][1] + bb.y,
                               acc[i][2] + bb.z, acc[i][3] + bb.w);
        *(float4*)&Y[(size_t)(m0 + r0 + i) * DD + n0 + c0] = v;
    }
}

// ---------------------------------------------------------------------------
extern "C" void kernel_launch(void* const* d_in, const int* in_sizes, int n_in,
                              void* d_out, int out_size) {
    const float* q  = (const float*)d_in[0];
    const float* k  = (const float*)d_in[1];
    const float* v  = (const float*)d_in[2];
    const float* Wq = (const float*)d_in[3];
    const float* Wk = (const float*)d_in[4];
    const float* Wv = (const float*)d_in[5];
    const float* Wo = (const float*)d_in[6];
    const float* bo = (const float*)d_in[7];
    float* out = (float*)d_out;

    float *Qp, *Kp, *Vp, *AOp;
    cudaGetSymbolAddress((void**)&Qp, g_Q);
    cudaGetSymbolAddress((void**)&Kp, g_K);
    cudaGetSymbolAddress((void**)&Vp, g_V);
    cudaGetSymbolAddress((void**)&AOp, g_AO);

    const int M = BB * SS;            // 8192
    dim3 gp(M / 64, HH);              // (128, 16)
    proj_kernel<<<gp, 256>>>(q, Wq, Qp);
    proj_kernel<<<gp, 256>>>(k, Wk, Kp);
    proj_kernel<<<gp, 256>>>(v, Wv, Vp);

    size_t fsm = (size_t)3 * 64 * 68 * sizeof(float);  // 52224 B
    cudaFuncSetAttribute(flash_kernel, cudaFuncAttributeMaxDynamicSharedMemorySize,
                         (int)fsm);
    flash_kernel<<<dim3(SS / 64, BB * HH), 256, fsm>>>(Qp, Kp, Vp, AOp);

    outproj_kernel<<<dim3(M / 64, DD / 64), 256>>>(AOp, Wo, bo, out);
}

// round 7
// speedup vs baseline: 2.1799x; 2.1799x over previous
#include <cuda_runtime.h>
#include <math.h>
#include <stdint.h>

#define BB 4
#define SS 2048
#define DD 1024
#define HH 16
#define HD 64

// ---------------- scratch (device globals; no allocations allowed) ----------
__device__ float g_Q[(size_t)BB * HH * SS * HD];   // [B,H,S,64]
__device__ float g_K[(size_t)BB * HH * SS * HD];
__device__ float g_V[(size_t)BB * HH * SS * HD];
__device__ float g_AO[(size_t)BB * SS * DD];       // [B,S,H*64]
__device__ float g_Wqt[(size_t)DD * DD];           // [h*64+n][k] f32
__device__ float g_Wkt[(size_t)DD * DD];
__device__ float g_Wvt[(size_t)DD * DD];

// ---------------- helpers ---------------------------------------------------
__device__ __forceinline__ uint32_t smem_u32(const void* p) {
    uint32_t a;
    asm("{ .reg .u64 t; cvta.to.shared.u64 t, %1; cvt.u32.u64 %0, t; }"
        : "=r"(a) : "l"(p));
    return a;
}
__device__ __forceinline__ void cpa16(uint32_t dst, const void* src) {
    asm volatile("cp.async.cg.shared.global [%0], [%1], 16;" :: "r"(dst), "l"(src));
}
#define CPA_COMMIT() asm volatile("cp.async.commit_group;" ::: "memory")
#define CPA_WAIT1()  asm volatile("cp.async.wait_group 1;" ::: "memory")
#define CPA_WAIT0()  asm volatile("cp.async.wait_group 0;" ::: "memory")

#define MMA_TF32(d, a, b)                                                      \
    asm volatile("mma.sync.aligned.m16n8k8.row.col.f32.tf32.tf32.f32 "         \
        "{%0,%1,%2,%3}, {%4,%5,%6,%7}, {%8,%9}, {%0,%1,%2,%3};"                \
        : "+f"((d)[0]), "+f"((d)[1]), "+f"((d)[2]), "+f"((d)[3])               \
        : "r"((a)[0]), "r"((a)[1]), "r"((a)[2]), "r"((a)[3]),                  \
          "r"((b)[0]), "r"((b)[1]))

// hi/lo split for 3xTF32: hi is exactly tf32-representable, lo is the residual
__device__ __forceinline__ void tf32_split(float a, uint32_t& hi, uint32_t& lo) {
    uint32_t h = __float_as_uint(a) & 0xFFFFE000u;
    hi = h;
    lo = __float_as_uint(a - __uint_as_float(h));
}

// smem: As[2][128][36], Bs[2][128][36] floats
#define TSTRIDE 36
#define BUF_FLOATS (128 * TSTRIDE)          // 4608
#define BUF_BYTES  (BUF_FLOATS * 4)         // 18432
#define GSM_TOTAL  (4 * BUF_BYTES)          // 73728

// ---------------------------------------------------------------------------
// 3xTF32 mma.sync GEMM: C[m,n] = sum_k A[m,k] * Bt[n,k]
// CTA 128x128, k-tile 32, double-buffered cp.async.
// mode 0: scatter to [B,H,S,64]; mode 1: row-major [m][n] + bias.
// ---------------------------------------------------------------------------
__global__ __launch_bounds__(256) void gemm_mma_kernel(
    const float* __restrict__ A, const float* __restrict__ Bt,
    float* __restrict__ O, const float* __restrict__ bias, int mode)
{
    extern __shared__ float sm[];
    const uint32_t sbase = smem_u32(sm);

    const int tid = threadIdx.x;
    const int m0 = blockIdx.x * 128;
    const int n0 = blockIdx.y * 128;
    const int lane = tid & 31, wid = tid >> 5;
    const int g = lane >> 2, c = lane & 3;
    const int wm = (wid & 1) * 64;      // warp m offset
    const int wn = (wid >> 1) * 32;     // warp n offset

    const int lrow = tid >> 3;          // 0..31
    const int lch  = tid & 7;           // 0..7 (16B chunks of 32 floats)
    const float* Ag = A  + (size_t)(m0 + lrow) * DD + lch * 4;
    const float* Bg = Bt + (size_t)(n0 + lrow) * DD + lch * 4;

    float d[4][4][4];
#pragma unroll
    for (int mt = 0; mt < 4; mt++)
#pragma unroll
        for (int nt = 0; nt < 4; nt++)
#pragma unroll
            for (int i = 0; i < 4; i++) d[mt][nt][i] = 0.f;

    auto load_tile = [&](int t, int buf) {
        const int k0 = t * 32;
        const uint32_t sa = sbase + buf * BUF_BYTES + (lrow * TSTRIDE + lch * 4) * 4;
        const uint32_t sb = sbase + 2 * BUF_BYTES + buf * BUF_BYTES +
                            (lrow * TSTRIDE + lch * 4) * 4;
#pragma unroll
        for (int r = 0; r < 4; r++) {
            cpa16(sa + r * 32 * TSTRIDE * 4, Ag + (size_t)r * 32 * DD + k0);
            cpa16(sb + r * 32 * TSTRIDE * 4, Bg + (size_t)r * 32 * DD + k0);
        }
    };

    load_tile(0, 0);
    CPA_COMMIT();

    const int NT = DD / 32;  // 32
    for (int t = 0; t < NT; t++) {
        const int buf = t & 1;
        if (t + 1 < NT) {
            load_tile(t + 1, (t + 1) & 1);
            CPA_COMMIT();
            CPA_WAIT1();
        } else {
            CPA_WAIT0();
        }
        __syncthreads();

        const float* as = sm + buf * BUF_FLOATS;
        const float* bs = sm + 2 * BUF_FLOATS + buf * BUF_FLOATS;
#pragma unroll
        for (int kk = 0; kk < 32; kk += 8) {
            uint32_t afh[4][4], afl[4][4], bfh[4][2], bfl[4][2];
#pragma unroll
            for (int mt = 0; mt < 4; mt++) {
                const int rb = wm + mt * 16 + g;
                tf32_split(as[rb * TSTRIDE + kk + c],           afh[mt][0], afl[mt][0]);
                tf32_split(as[(rb + 8) * TSTRIDE + kk + c],     afh[mt][1], afl[mt][1]);
                tf32_split(as[rb * TSTRIDE + kk + c + 4],       afh[mt][2], afl[mt][2]);
                tf32_split(as[(rb + 8) * TSTRIDE + kk + c + 4], afh[mt][3], afl[mt][3]);
            }
#pragma unroll
            for (int nt = 0; nt < 4; nt++) {
                const int nb = wn + nt * 8 + g;
                tf32_split(bs[nb * TSTRIDE + kk + c],     bfh[nt][0], bfl[nt][0]);
                tf32_split(bs[nb * TSTRIDE + kk + c + 4], bfh[nt][1], bfl[nt][1]);
            }
            // correction terms first, then the dominant hi*hi
#pragma unroll
            for (int mt = 0; mt < 4; mt++)
#pragma unroll
                for (int nt = 0; nt < 4; nt++)
                    MMA_TF32(d[mt][nt], afh[mt], bfl[nt]);
#pragma unroll
            for (int mt = 0; mt < 4; mt++)
#pragma unroll
                for (int nt = 0; nt < 4; nt++)
                    MMA_TF32(d[mt][nt], afl[mt], bfh[nt]);
#pragma unroll
            for (int mt = 0; mt < 4; mt++)
#pragma unroll
                for (int nt = 0; nt < 4; nt++)
                    MMA_TF32(d[mt][nt], afh[mt], bfh[nt]);
        }
        __syncthreads();
    }

    // epilogue: d0/d1 = (row g, cols 2c,2c+1); d2/d3 = (row g+8, same cols)
#pragma unroll
    for (int mt = 0; mt < 4; mt++) {
        const int r1 = m0 + wm + mt * 16 + g;
        const int r2 = r1 + 8;
#pragma unroll
        for (int nt = 0; nt < 4; nt++) {
            const int cg = n0 + wn + nt * 8 + c * 2;
            if (mode == 0) {
                const int h = cg >> 6, hn = cg & 63;
                const int b1 = r1 >> 11, s1 = r1 & (SS - 1);
                const int b2 = r2 >> 11, s2 = r2 & (SS - 1);
                float* p1 = O + (((size_t)(b1 * HH + h) * SS + s1) * HD + hn);
                float* p2 = O + (((size_t)(b2 * HH + h) * SS + s2) * HD + hn);
                *(float2*)p1 = make_float2(d[mt][nt][0], d[mt][nt][1]);
                *(float2*)p2 = make_float2(d[mt][nt][2], d[mt][nt][3]);
            } else {
                float2 bb = *(const float2*)(bias + cg);
                *(float2*)(O + (size_t)r1 * DD + cg) =
                    make_float2(d[mt][nt][0] + bb.x, d[mt][nt][1] + bb.y);
                *(float2*)(O + (size_t)r2 * DD + cg) =
                    make_float2(d[mt][nt][2] + bb.x, d[mt][nt][3] + bb.y);
            }
        }
    }
}

// ---------------------------------------------------------------------------
// W [16,1024,64] -> Wt [h*64+n][k]  (transpose, f32)
// ---------------------------------------------------------------------------
__global__ void wtrans_kernel(const float* __restrict__ W, float* __restrict__ Wt) {
    __shared__ float t[32][33];
    const int h = blockIdx.z, k0 = blockIdx.x * 32, n0 = blockIdx.y * 32;
    const int tx = threadIdx.x, ty = threadIdx.y;
#pragma unroll
    for (int i = ty; i < 32; i += 8)
        t[i][tx] = W[((size_t)h * DD + k0 + i) * HD + n0 + tx];
    __syncthreads();
#pragma unroll
    for (int i = ty; i < 32; i += 8)
        Wt[(size_t)(h * HD + n0 + i) * DD + k0 + tx] = t[tx][i];
}

// ---------------------------------------------------------------------------
// Causal flash attention, fp32 (unchanged — known correct)
// ---------------------------------------------------------------------------
__global__ __launch_bounds__(256) void flash_kernel(const float* __restrict__ Q,
                                                    const float* __restrict__ K,
                                                    const float* __restrict__ V,
                                                    float* __restrict__ AO) {
    extern __shared__ float sm[];
    float* QsT = sm;
    float* KsT = sm + 64 * 68;
    float* Vs  = sm + 2 * 64 * 68;

    const int qi  = (int)gridDim.x - 1 - (int)blockIdx.x;
    const int bh  = blockIdx.y;
    const int b   = bh >> 4, h = bh & 15;
    const int qm0 = qi * 64;

    const float* Qh = Q + (size_t)bh * SS * HD;
    const float* Kh = K + (size_t)bh * SS * HD;
    const float* Vh = V + (size_t)bh * SS * HD;

    const int tid = threadIdx.x;
    const int tx = tid & 15, ty = tid >> 4;
    const int r0 = ty * 4, c0 = tx * 4;
    const int ls = tid >> 2;
    const int ld4 = (tid & 3) * 4;

    {
        const float* qp = Qh + (size_t)(qm0 + ls) * HD + ld4;
#pragma unroll
        for (int it = 0; it < 4; it++) {
            float4 v4 = *(const float4*)(qp + it * 16);
            int d = ld4 + it * 16;
            QsT[(d + 0) * 68 + ls] = v4.x;
            QsT[(d + 1) * 68 + ls] = v4.y;
            QsT[(d + 2) * 68 + ls] = v4.z;
            QsT[(d + 3) * 68 + ls] = v4.w;
        }
    }

    float m_[4], l_[4], o[4][4];
#pragma unroll
    for (int i = 0; i < 4; i++) {
        m_[i] = -1e30f; l_[i] = 0.f;
#pragma unroll
        for (int j = 0; j < 4; j++) o[i][j] = 0.f;
    }

    for (int kt = 0; kt <= qi; kt++) {
        const int kn0 = kt * 64;
        __syncthreads();
        {
            const float* kp = Kh + (size_t)(kn0 + ls) * HD + ld4;
            const float* vp = Vh + (size_t)(kn0 + ls) * HD + ld4;
#pragma unroll
            for (int it = 0; it < 4; it++) {
                float4 kv = *(const float4*)(kp + it * 16);
                int d = ld4 + it * 16;
                KsT[(d + 0) * 68 + ls] = kv.x;
                KsT[(d + 1) * 68 + ls] = kv.y;
                KsT[(d + 2) * 68 + ls] = kv.z;
                KsT[(d + 3) * 68 + ls] = kv.w;
                float4 vv = *(const float4*)(vp + it * 16);
                *(float4*)&Vs[ls * 68 + d] = vv;
            }
        }
        __syncthreads();

        float s4[4][4];
#pragma unroll
        for (int i = 0; i < 4; i++)
#pragma unroll
            for (int j = 0; j < 4; j++) s4[i][j] = 0.f;

        for (int d = 0; d < 64; d++) {
            float4 qa = *(float4*)&QsT[d * 68 + r0];
            float4 kb = *(float4*)&KsT[d * 68 + c0];
            float a[4] = {qa.x, qa.y, qa.z, qa.w};
            float cc[4] = {kb.x, kb.y, kb.z, kb.w};
#pragma unroll
            for (int i = 0; i < 4; i++)
#pragma unroll
                for (int j = 0; j < 4; j++)
                    s4[i][j] = fmaf(a[i], cc[j], s4[i][j]);
        }

        const float scale = 0.125f;
        if (kt == qi) {
#pragma unroll
            for (int i = 0; i < 4; i++)
#pragma unroll
                for (int j = 0; j < 4; j++)
                    s4[i][j] = (c0 + j > r0 + i) ? -1e30f : s4[i][j] * scale;
        } else {
#pragma unroll
            for (int i = 0; i < 4; i++)
#pragma unroll
                for (int j = 0; j < 4; j++) s4[i][j] *= scale;
        }

#pragma unroll
        for (int i = 0; i < 4; i++) {
            float mx = fmaxf(fmaxf(s4[i][0], s4[i][1]), fmaxf(s4[i][2], s4[i][3]));
#pragma unroll
            for (int off = 1; off < 16; off <<= 1)
                mx = fmaxf(mx, __shfl_xor_sync(0xffffffffu, mx, off));
            float mn = fmaxf(m_[i], mx);
            float alpha = __expf(m_[i] - mn);
            m_[i] = mn;
            float rs = 0.f;
#pragma unroll
            for (int j = 0; j < 4; j++) {
                float pv = __expf(s4[i][j] - mn);
                s4[i][j] = pv;
                rs += pv;
            }
#pragma unroll
            for (int off = 1; off < 16; off <<= 1)
                rs += __shfl_xor_sync(0xffffffffu, rs, off);
            l_[i] = l_[i] * alpha + rs;
#pragma unroll
            for (int j = 0; j < 4; j++) o[i][j] *= alpha;
        }

        __syncthreads();
#pragma unroll
        for (int i = 0; i < 4; i++)
#pragma unroll
            for (int j = 0; j < 4; j++)
                KsT[(c0 + j) * 68 + (r0 + i)] = s4[i][j];
        __syncthreads();

        for (int k = 0; k < 64; k++) {
            float4 pr = *(float4*)&KsT[k * 68 + r0];
            float4 vv = *(float4*)&Vs[k * 68 + c0];
            float p[4] = {pr.x, pr.y, pr.z, pr.w};
            float v4[4] = {vv.x, vv.y, vv.z, vv.w};
#pragma unroll
            for (int i = 0; i < 4; i++)
#pragma unroll
                for (int j = 0; j < 4; j++)
                    o[i][j] = fmaf(p[i], v4[j], o[i][j]);
        }
    }

#pragma unroll
    for (int i = 0; i < 4; i++) {
        float inv = 1.f / l_[i];
        float4 v = make_float4(o[i][0] * inv, o[i][1] * inv, o[i][2] * inv, o[i][3] * inv);
        size_t s = (size_t)qm0 + r0 + i;
        *(float4*)&AO[((size_t)b * SS + s) * DD + h * HD + c0] = v;
    }
}

// ---------------------------------------------------------------------------
extern "C" void kernel_launch(void* const* d_in, const int* in_sizes, int n_in,
                              void* d_out, int out_size) {
    const float* q  = (const float*)d_in[0];
    const float* k  = (const float*)d_in[1];
    const float* v  = (const float*)d_in[2];
    const float* Wq = (const float*)d_in[3];
    const float* Wk = (const float*)d_in[4];
    const float* Wv = (const float*)d_in[5];
    const float* Wo = (const float*)d_in[6];
    const float* bo = (const float*)d_in[7];
    float* out = (float*)d_out;

    float *Qp, *Kp, *Vp, *AOp, *Wqt, *Wkt, *Wvt;
    cudaGetSymbolAddress((void**)&Qp, g_Q);
    cudaGetSymbolAddress((void**)&Kp, g_K);
    cudaGetSymbolAddress((void**)&Vp, g_V);
    cudaGetSymbolAddress((void**)&AOp, g_AO);
    cudaGetSymbolAddress((void**)&Wqt, g_Wqt);
    cudaGetSymbolAddress((void**)&Wkt, g_Wkt);
    cudaGetSymbolAddress((void**)&Wvt, g_Wvt);

    // weight prep: transpose to [h*64+n][k]
    dim3 tb(32, 8);
    dim3 tg(DD / 32, HD / 32, HH);
    wtrans_kernel<<<tg, tb>>>(Wq, Wqt);
    wtrans_kernel<<<tg, tb>>>(Wk, Wkt);
    wtrans_kernel<<<tg, tb>>>(Wv, Wvt);

    cudaFuncSetAttribute(gemm_mma_kernel,
                         cudaFuncAttributeMaxDynamicSharedMemorySize, GSM_TOTAL);

    const int M = BB * SS;                 // 8192
    dim3 gg(M / 128, DD / 128);            // (64, 8)
    gemm_mma_kernel<<<gg, 256, GSM_TOTAL>>>(q, Wqt, Qp, bo, 0);
    gemm_mma_kernel<<<gg, 256, GSM_TOTAL>>>(k, Wkt, Kp, bo, 0);
    gemm_mma_kernel<<<gg, 256, GSM_TOTAL>>>(v, Wvt, Vp, bo, 0);

    size_t fsm = (size_t)3 * 64 * 68 * sizeof(float);
    cudaFuncSetAttribute(flash_kernel, cudaFuncAttributeMaxDynamicSharedMemorySize,
                         (int)fsm);
    flash_kernel<<<dim3(SS / 64, BB * HH), 256, fsm>>>(Qp, Kp, Vp, AOp);

    // out-projection: Wo is already [n][k] for Y = AO @ Wo^T
    gemm_mma_kernel<<<gg, 256, GSM_TOTAL>>>(AOp, Wo, out, bo, 1);
}

// round 9
// speedup vs baseline: 2.4316x; 1.1154x over previous
#include <cuda_runtime.h>
#include <cuda_bf16.h>
#include <math.h>
#include <stdint.h>

#define BB 4
#define SS 2048
#define DD 1024
#define HH 16
#define HD 64

// ---------------- scratch (device globals; no allocations allowed) ----------
__device__ float    g_Q[(size_t)BB * HH * SS * HD];   // [B,H,S,64] f32
__device__ float    g_K[(size_t)BB * HH * SS * HD];
__device__ float    g_V[(size_t)BB * HH * SS * HD];
__device__ uint32_t g_AO[(size_t)BB * SS * DD];       // [B,S,H*64] packed bf16 hi|lo
__device__ uint32_t g_Pq[(size_t)BB * SS * DD];       // packed inputs
__device__ uint32_t g_Pk[(size_t)BB * SS * DD];
__device__ uint32_t g_Pv[(size_t)BB * SS * DD];
__device__ uint32_t g_Wqt[(size_t)DD * DD];           // [h*64+n][k] packed
__device__ uint32_t g_Wkt[(size_t)DD * DD];
__device__ uint32_t g_Wvt[(size_t)DD * DD];
__device__ uint32_t g_Wot[(size_t)DD * DD];           // [n][k] packed

// single dynamic smem symbol shared by all kernels
extern __shared__ char dynsm[];

// ---------------- helpers ---------------------------------------------------
__device__ __forceinline__ uint32_t smem_u32(const void* p) {
    uint32_t a;
    asm("{ .reg .u64 t; cvta.to.shared.u64 t, %1; cvt.u32.u64 %0, t; }"
        : "=r"(a) : "l"(p));
    return a;
}
__device__ __forceinline__ void cpa16(uint32_t dst, const void* src) {
    asm volatile("cp.async.cg.shared.global [%0], [%1], 16;" :: "r"(dst), "l"(src));
}
#define CPA_COMMIT() asm volatile("cp.async.commit_group;" ::: "memory")
#define CPA_WAIT1()  asm volatile("cp.async.wait_group 1;" ::: "memory")
#define CPA_WAIT0()  asm volatile("cp.async.wait_group 0;" ::: "memory")

#define MMA_BF16(d, a, b)                                                      \
    asm volatile("mma.sync.aligned.m16n8k16.row.col.f32.bf16.bf16.f32 "        \
        "{%0,%1,%2,%3}, {%4,%5,%6,%7}, {%8,%9}, {%0,%1,%2,%3};"                \
        : "+f"((d)[0]), "+f"((d)[1]), "+f"((d)[2]), "+f"((d)[3])               \
        : "r"((a)[0]), "r"((a)[1]), "r"((a)[2]), "r"((a)[3]),                  \
          "r"((b)[0]), "r"((b)[1]))

// pack f32 -> (bf16_hi << 16) | bf16_lo ; hi = rn(x), lo = rn(x - hi)
__device__ __forceinline__ uint32_t pack_bf16split(float x) {
    uint32_t h = (uint32_t)__bfloat16_as_ushort(__float2bfloat16_rn(x));
    float hf = __uint_as_float(h << 16);
    uint32_t l = (uint32_t)__bfloat16_as_ushort(__float2bfloat16_rn(x - hf));
    return (h << 16) | l;
}

// smem: As[2][128][36], Bs[2][128][36] packed u32
#define TSTRIDE 36
#define BUF_WORDS (128 * TSTRIDE)           // 4608
#define BUF_BYTES (BUF_WORDS * 4)           // 18432
#define GSM_TOTAL (4 * BUF_BYTES)           // 73728

// ---------------------------------------------------------------------------
// 3xBF16 mma.sync GEMM: C[m,n] = sum_k A[m,k] * Bt[n,k]  (operands prepacked)
// CTA 128x128, k-tile 32, double-buffered cp.async.
// mode 0: scatter to [B,H,S,64]; mode 1: row-major [m][n] + bias.
// ---------------------------------------------------------------------------
__global__ __launch_bounds__(256) void gemm_bf16_kernel(
    const uint32_t* __restrict__ A, const uint32_t* __restrict__ Bt,
    float* __restrict__ O, const float* __restrict__ bias, int mode)
{
    uint32_t* sm = (uint32_t*)dynsm;
    const uint32_t sbase = smem_u32(sm);

    const int tid = threadIdx.x;
    const int m0 = blockIdx.x * 128;
    const int n0 = blockIdx.y * 128;
    const int lane = tid & 31, wid = tid >> 5;
    const int g = lane >> 2, c = lane & 3;
    const int wm = (wid & 1) * 64;      // warp m offset
    const int wn = (wid >> 1) * 32;     // warp n offset

    const int lrow = tid >> 3;          // 0..31
    const int lch  = tid & 7;           // 0..7 (16B chunks of a 32-word row)
    const uint32_t* Ag = A  + (size_t)(m0 + lrow) * DD + lch * 4;
    const uint32_t* Bg = Bt + (size_t)(n0 + lrow) * DD + lch * 4;

    float d[4][4][4];
#pragma unroll
    for (int mt = 0; mt < 4; mt++)
#pragma unroll
        for (int nt = 0; nt < 4; nt++)
#pragma unroll
            for (int i = 0; i < 4; i++) d[mt][nt][i] = 0.f;

    auto load_tile = [&](int t, int buf) {
        const int k0 = t * 32;
        const uint32_t sa = sbase + buf * BUF_BYTES + (lrow * TSTRIDE + lch * 4) * 4;
        const uint32_t sb = sbase + 2 * BUF_BYTES + buf * BUF_BYTES +
                            (lrow * TSTRIDE + lch * 4) * 4;
#pragma unroll
        for (int r = 0; r < 4; r++) {
            cpa16(sa + r * 32 * TSTRIDE * 4, Ag + (size_t)r * 32 * DD + k0);
            cpa16(sb + r * 32 * TSTRIDE * 4, Bg + (size_t)r * 32 * DD + k0);
        }
    };

    load_tile(0, 0);
    CPA_COMMIT();

    const int NT = DD / 32;  // 32
    for (int t = 0; t < NT; t++) {
        const int buf = t & 1;
        if (t + 1 < NT) {
            load_tile(t + 1, (t + 1) & 1);
            CPA_COMMIT();
            CPA_WAIT1();
        } else {
            CPA_WAIT0();
        }
        __syncthreads();

        const uint32_t* as = sm + buf * BUF_WORDS;
        const uint32_t* bs = sm + 2 * BUF_WORDS + buf * BUF_WORDS;
#pragma unroll
        for (int kk = 0; kk < 32; kk += 16) {
            uint32_t ah[4][4], al[4][4], bh[4][2], bl[4][2];
#pragma unroll
            for (int mt = 0; mt < 4; mt++) {
                const int rb = wm + mt * 16 + g;
                uint2 p0 = *(const uint2*)&as[rb * TSTRIDE + kk + 2 * c];
                uint2 p1 = *(const uint2*)&as[(rb + 8) * TSTRIDE + kk + 2 * c];
                uint2 p2 = *(const uint2*)&as[rb * TSTRIDE + kk + 2 * c + 8];
                uint2 p3 = *(const uint2*)&as[(rb + 8) * TSTRIDE + kk + 2 * c + 8];
                ah[mt][0] = __byte_perm(p0.x, p0.y, 0x7632);
                al[mt][0] = __byte_perm(p0.x, p0.y, 0x5410);
                ah[mt][1] = __byte_perm(p1.x, p1.y, 0x7632);
                al[mt][1] = __byte_perm(p1.x, p1.y, 0x5410);
                ah[mt][2] = __byte_perm(p2.x, p2.y, 0x7632);
                al[mt][2] = __byte_perm(p2.x, p2.y, 0x5410);
                ah[mt][3] = __byte_perm(p3.x, p3.y, 0x7632);
                al[mt][3] = __byte_perm(p3.x, p3.y, 0x5410);
            }
#pragma unroll
            for (int nt = 0; nt < 4; nt++) {
                const int nb = wn + nt * 8 + g;
                uint2 q0 = *(const uint2*)&bs[nb * TSTRIDE + kk + 2 * c];
                uint2 q1 = *(const uint2*)&bs[nb * TSTRIDE + kk + 2 * c + 8];
                bh[nt][0] = __byte_perm(q0.x, q0.y, 0x7632);
                bl[nt][0] = __byte_perm(q0.x, q0.y, 0x5410);
                bh[nt][1] = __byte_perm(q1.x, q1.y, 0x7632);
                bl[nt][1] = __byte_perm(q1.x, q1.y, 0x5410);
            }
            // correction terms first, then the dominant hi*hi
#pragma unroll
            for (int mt = 0; mt < 4; mt++)
#pragma unroll
                for (int nt = 0; nt < 4; nt++)
                    MMA_BF16(d[mt][nt], ah[mt], bl[nt]);
#pragma unroll
            for (int mt = 0; mt < 4; mt++)
#pragma unroll
                for (int nt = 0; nt < 4; nt++)
                    MMA_BF16(d[mt][nt], al[mt], bh[nt]);
#pragma unroll
            for (int mt = 0; mt < 4; mt++)
#pragma unroll
                for (int nt = 0; nt < 4; nt++)
                    MMA_BF16(d[mt][nt], ah[mt], bh[nt]);
        }
        __syncthreads();
    }

    // epilogue: d0/d1 = (row g, cols 2c,2c+1); d2/d3 = (row g+8, same cols)
#pragma unroll
    for (int mt = 0; mt < 4; mt++) {
        const int r1 = m0 + wm + mt * 16 + g;
        const int r2 = r1 + 8;
#pragma unroll
        for (int nt = 0; nt < 4; nt++) {
            const int cg = n0 + wn + nt * 8 + c * 2;
            if (mode == 0) {
                const int h = cg >> 6, hn = cg & 63;
                const int b1 = r1 >> 11, s1 = r1 & (SS - 1);
                const int b2 = r2 >> 11, s2 = r2 & (SS - 1);
                float* p1 = O + (((size_t)(b1 * HH + h) * SS + s1) * HD + hn);
                float* p2 = O + (((size_t)(b2 * HH + h) * SS + s2) * HD + hn);
                *(float2*)p1 = make_float2(d[mt][nt][0], d[mt][nt][1]);
                *(float2*)p2 = make_float2(d[mt][nt][2], d[mt][nt][3]);
            } else {
                float2 bb = *(const float2*)(bias + cg);
                *(float2*)(O + (size_t)r1 * DD + cg) =
                    make_float2(d[mt][nt][0] + bb.x, d[mt][nt][1] + bb.y);
                *(float2*)(O + (size_t)r2 * DD + cg) =
                    make_float2(d[mt][nt][2] + bb.x, d[mt][nt][3] + bb.y);
            }
        }
    }
}

// ---------------------------------------------------------------------------
// Pack f32 array -> bf16 hi/lo packed u32 (vectorized by 4)
// ---------------------------------------------------------------------------
__global__ void pack_kernel(const float* __restrict__ in, uint32_t* __restrict__ out) {
    int i = (blockIdx.x * 256 + threadIdx.x) * 4;
    float4 v = *(const float4*)(in + i);
    uint4 r;
    r.x = pack_bf16split(v.x);
    r.y = pack_bf16split(v.y);
    r.z = pack_bf16split(v.z);
    r.w = pack_bf16split(v.w);
    *(uint4*)(out + i) = r;
}

// ---------------------------------------------------------------------------
// W [16,1024,64] -> Wt [h*64+n][k]  (transpose + pack)
// ---------------------------------------------------------------------------
__global__ void wtrans_kernel(const float* __restrict__ W, uint32_t* __restrict__ Wt) {
    __shared__ float t[32][33];
    const int h = blockIdx.z, k0 = blockIdx.x * 32, n0 = blockIdx.y * 32;
    const int tx = threadIdx.x, ty = threadIdx.y;
#pragma unroll
    for (int i = ty; i < 32; i += 8)
        t[i][tx] = W[((size_t)h * DD + k0 + i) * HD + n0 + tx];
    __syncthreads();
#pragma unroll
    for (int i = ty; i < 32; i += 8)
        Wt[(size_t)(h * HD + n0 + i) * DD + k0 + tx] = pack_bf16split(t[tx][i]);
}

// ---------------------------------------------------------------------------
// Causal flash attention, fp32 (unchanged except packed AO epilogue)
// ---------------------------------------------------------------------------
__global__ __launch_bounds__(256) void flash_kernel(const float* __restrict__ Q,
                                                    const float* __restrict__ K,
                                                    const float* __restrict__ V,
                                                    uint32_t* __restrict__ AO) {
    float* sm = (float*)dynsm;
    float* QsT = sm;
    float* KsT = sm + 64 * 68;
    float* Vs  = sm + 2 * 64 * 68;

    const int qi  = (int)gridDim.x - 1 - (int)blockIdx.x;
    const int bh  = blockIdx.y;
    const int b   = bh >> 4, h = bh & 15;
    const int qm0 = qi * 64;

    const float* Qh = Q + (size_t)bh * SS * HD;
    const float* Kh = K + (size_t)bh * SS * HD;
    const float* Vh = V + (size_t)bh * SS * HD;

    const int tid = threadIdx.x;
    const int tx = tid & 15, ty = tid >> 4;
    const int r0 = ty * 4, c0 = tx * 4;
    const int ls = tid >> 2;
    const int ld4 = (tid & 3) * 4;

    {
        const float* qp = Qh + (size_t)(qm0 + ls) * HD + ld4;
#pragma unroll
        for (int it = 0; it < 4; it++) {
            float4 v4 = *(const float4*)(qp + it * 16);
            int d = ld4 + it * 16;
            QsT[(d + 0) * 68 + ls] = v4.x;
            QsT[(d + 1) * 68 + ls] = v4.y;
            QsT[(d + 2) * 68 + ls] = v4.z;
            QsT[(d + 3) * 68 + ls] = v4.w;
        }
    }

    float m_[4], l_[4], o[4][4];
#pragma unroll
    for (int i = 0; i < 4; i++) {
        m_[i] = -1e30f; l_[i] = 0.f;
#pragma unroll
        for (int j = 0; j < 4; j++) o[i][j] = 0.f;
    }

    for (int kt = 0; kt <= qi; kt++) {
        const int kn0 = kt * 64;
        __syncthreads();
        {
            const float* kp = Kh + (size_t)(kn0 + ls) * HD + ld4;
            const float* vp = Vh + (size_t)(kn0 + ls) * HD + ld4;
#pragma unroll
            for (int it = 0; it < 4; it++) {
                float4 kv = *(const float4*)(kp + it * 16);
                int d = ld4 + it * 16;
                KsT[(d + 0) * 68 + ls] = kv.x;
                KsT[(d + 1) * 68 + ls] = kv.y;
                KsT[(d + 2) * 68 + ls] = kv.z;
                KsT[(d + 3) * 68 + ls] = kv.w;
                float4 vv = *(const float4*)(vp + it * 16);
                *(float4*)&Vs[ls * 68 + d] = vv;
            }
        }
        __syncthreads();

        float s4[4][4];
#pragma unroll
        for (int i = 0; i < 4; i++)
#pragma unroll
            for (int j = 0; j < 4; j++) s4[i][j] = 0.f;

        for (int d = 0; d < 64; d++) {
            float4 qa = *(float4*)&QsT[d * 68 + r0];
            float4 kb = *(float4*)&KsT[d * 68 + c0];
            float a[4] = {qa.x, qa.y, qa.z, qa.w};
            float cc[4] = {kb.x, kb.y, kb.z, kb.w};
#pragma unroll
            for (int i = 0; i < 4; i++)
#pragma unroll
                for (int j = 0; j < 4; j++)
                    s4[i][j] = fmaf(a[i], cc[j], s4[i][j]);
        }

        const float scale = 0.125f;
        if (kt == qi) {
#pragma unroll
            for (int i = 0; i < 4; i++)
#pragma unroll
                for (int j = 0; j < 4; j++)
                    s4[i][j] = (c0 + j > r0 + i) ? -1e30f : s4[i][j] * scale;
        } else {
#pragma unroll
            for (int i = 0; i < 4; i++)
#pragma unroll
                for (int j = 0; j < 4; j++) s4[i][j] *= scale;
        }

#pragma unroll
        for (int i = 0; i < 4; i++) {
            float mx = fmaxf(fmaxf(s4[i][0], s4[i][1]), fmaxf(s4[i][2], s4[i][3]));
#pragma unroll
            for (int off = 1; off < 16; off <<= 1)
                mx = fmaxf(mx, __shfl_xor_sync(0xffffffffu, mx, off));
            float mn = fmaxf(m_[i], mx);
            float alpha = __expf(m_[i] - mn);
            m_[i] = mn;
            float rs = 0.f;
#pragma unroll
            for (int j = 0; j < 4; j++) {
                float pv = __expf(s4[i][j] - mn);
                s4[i][j] = pv;
                rs += pv;
            }
#pragma unroll
            for (int off = 1; off < 16; off <<= 1)
                rs += __shfl_xor_sync(0xffffffffu, rs, off);
            l_[i] = l_[i] * alpha + rs;
#pragma unroll
            for (int j = 0; j < 4; j++) o[i][j] *= alpha;
        }

        __syncthreads();
#pragma unroll
        for (int i = 0; i < 4; i++)
#pragma unroll
            for (int j = 0; j < 4; j++)
                KsT[(c0 + j) * 68 + (r0 + i)] = s4[i][j];
        __syncthreads();

        for (int k = 0; k < 64; k++) {
            float4 pr = *(float4*)&KsT[k * 68 + r0];
            float4 vv = *(float4*)&Vs[k * 68 + c0];
            float p[4] = {pr.x, pr.y, pr.z, pr.w};
            float v4[4] = {vv.x, vv.y, vv.z, vv.w};
#pragma unroll
            for (int i = 0; i < 4; i++)
#pragma unroll
                for (int j = 0; j < 4; j++)
                    o[i][j] = fmaf(p[i], v4[j], o[i][j]);
        }
    }

    // epilogue: normalize + pack bf16 hi/lo for the out-projection GEMM
#pragma unroll
    for (int i = 0; i < 4; i++) {
        float inv = 1.f / l_[i];
        uint4 v;
        v.x = pack_bf16split(o[i][0] * inv);
        v.y = pack_bf16split(o[i][1] * inv);
        v.z = pack_bf16split(o[i][2] * inv);
        v.w = pack_bf16split(o[i][3] * inv);
        size_t s = (size_t)qm0 + r0 + i;
        *(uint4*)&AO[((size_t)b * SS + s) * DD + h * HD + c0] = v;
    }
}

// ---------------------------------------------------------------------------
extern "C" void kernel_launch(void* const* d_in, const int* in_sizes, int n_in,
                              void* d_out, int out_size) {
    const float* q  = (const float*)d_in[0];
    const float* k  = (const float*)d_in[1];
    const float* v  = (const float*)d_in[2];
    const float* Wq = (const float*)d_in[3];
    const float* Wk = (const float*)d_in[4];
    const float* Wv = (const float*)d_in[5];
    const float* Wo = (const float*)d_in[6];
    const float* bo = (const float*)d_in[7];
    float* out = (float*)d_out;

    float *Qp, *Kp, *Vp;
    uint32_t *AOp, *Pq, *Pk, *Pv, *Wqt, *Wkt, *Wvt, *Wot;
    cudaGetSymbolAddress((void**)&Qp, g_Q);
    cudaGetSymbolAddress((void**)&Kp, g_K);
    cudaGetSymbolAddress((void**)&Vp, g_V);
    cudaGetSymbolAddress((void**)&AOp, g_AO);
    cudaGetSymbolAddress((void**)&Pq, g_Pq);
    cudaGetSymbolAddress((void**)&Pk, g_Pk);
    cudaGetSymbolAddress((void**)&Pv, g_Pv);
    cudaGetSymbolAddress((void**)&Wqt, g_Wqt);
    cudaGetSymbolAddress((void**)&Wkt, g_Wkt);
    cudaGetSymbolAddress((void**)&Wvt, g_Wvt);
    cudaGetSymbolAddress((void**)&Wot, g_Wot);

    const int M = BB * SS;                 // 8192
    const int NELEM = M * DD;              // 8.39M

    // prepack activations + weights
    pack_kernel<<<NELEM / 1024, 256>>>(q, Pq);
    pack_kernel<<<NELEM / 1024, 256>>>(k, Pk);
    pack_kernel<<<NELEM / 1024, 256>>>(v, Pv);
    pack_kernel<<<DD * DD / 1024, 256>>>(Wo, Wot);
    dim3 tb(32, 8);
    dim3 tg(DD / 32, HD / 32, HH);
    wtrans_kernel<<<tg, tb>>>(Wq, Wqt);
    wtrans_kernel<<<tg, tb>>>(Wk, Wkt);
    wtrans_kernel<<<tg, tb>>>(Wv, Wvt);

    cudaFuncSetAttribute(gemm_bf16_kernel,
                         cudaFuncAttributeMaxDynamicSharedMemorySize, GSM_TOTAL);

    dim3 gg(M / 128, DD / 128);            // (64, 8)
    gemm_bf16_kernel<<<gg, 256, GSM_TOTAL>>>(Pq, Wqt, Qp, bo, 0);
    gemm_bf16_kernel<<<gg, 256, GSM_TOTAL>>>(Pk, Wkt, Kp, bo, 0);
    gemm_bf16_kernel<<<gg, 256, GSM_TOTAL>>>(Pv, Wvt, Vp, bo, 0);

    size_t fsm = (size_t)3 * 64 * 68 * sizeof(float);
    cudaFuncSetAttribute(flash_kernel, cudaFuncAttributeMaxDynamicSharedMemorySize,
                         (int)fsm);
    flash_kernel<<<dim3(SS / 64, BB * HH), 256, fsm>>>(Qp, Kp, Vp, AOp);

    gemm_bf16_kernel<<<gg, 256, GSM_TOTAL>>>(AOp, Wot, out, bo, 1);
}

// round 10
// speedup vs baseline: 3.6498x; 1.5010x over previous
#include <cuda_runtime.h>
#include <cuda_bf16.h>
#include <math.h>
#include <stdint.h>

#define BB 4
#define SS 2048
#define DD 1024
#define HH 16
#define HD 64

// ---------------- scratch (device globals; no allocations allowed) ----------
__device__ uint32_t g_Qp[(size_t)BB * HH * SS * HD];  // [B,H,S,64] packed bf16 hi|lo
__device__ uint32_t g_Kp[(size_t)BB * HH * SS * HD];
__device__ uint32_t g_Vp[(size_t)BB * HH * SS * HD];
__device__ uint32_t g_AO[(size_t)BB * SS * DD];       // [B,S,H*64] packed
__device__ uint32_t g_Pq[(size_t)BB * SS * DD];       // packed inputs
__device__ uint32_t g_Pk[(size_t)BB * SS * DD];
__device__ uint32_t g_Pv[(size_t)BB * SS * DD];
__device__ uint32_t g_Wqt[(size_t)DD * DD];           // [h*64+n][k] packed
__device__ uint32_t g_Wkt[(size_t)DD * DD];
__device__ uint32_t g_Wvt[(size_t)DD * DD];
__device__ uint32_t g_Wot[(size_t)DD * DD];           // [n][k] packed

extern __shared__ char dynsm[];

// ---------------- helpers ---------------------------------------------------
__device__ __forceinline__ uint32_t smem_u32(const void* p) {
    uint32_t a;
    asm("{ .reg .u64 t; cvta.to.shared.u64 t, %1; cvt.u32.u64 %0, t; }"
        : "=r"(a) : "l"(p));
    return a;
}
__device__ __forceinline__ void cpa16(uint32_t dst, const void* src) {
    asm volatile("cp.async.cg.shared.global [%0], [%1], 16;" :: "r"(dst), "l"(src));
}
#define CPA_COMMIT() asm volatile("cp.async.commit_group;" ::: "memory")
#define CPA_WAIT1()  asm volatile("cp.async.wait_group 1;" ::: "memory")
#define CPA_WAIT0()  asm volatile("cp.async.wait_group 0;" ::: "memory")

#define MMA_BF16(d, a, b)                                                      \
    asm volatile("mma.sync.aligned.m16n8k16.row.col.f32.bf16.bf16.f32 "        \
        "{%0,%1,%2,%3}, {%4,%5,%6,%7}, {%8,%9}, {%0,%1,%2,%3};"                \
        : "+f"((d)[0]), "+f"((d)[1]), "+f"((d)[2]), "+f"((d)[3])               \
        : "r"((a)[0]), "r"((a)[1]), "r"((a)[2]), "r"((a)[3]),                  \
          "r"((b)[0]), "r"((b)[1]))

__device__ __forceinline__ uint32_t pack_bf16split(float x) {
    uint32_t h = (uint32_t)__bfloat16_as_ushort(__float2bfloat16_rn(x));
    float hf = __uint_as_float(h << 16);
    uint32_t l = (uint32_t)__bfloat16_as_ushort(__float2bfloat16_rn(x - hf));
    return (h << 16) | l;
}
// pack two f32 -> bf16x2, low half = lo arg
__device__ __forceinline__ uint32_t bf16x2(float lo, float hi) {
    uint32_t r;
    asm("cvt.rn.bf16x2.f32 %0, %1, %2;" : "=r"(r) : "f"(hi), "f"(lo));
    return r;
}
// split a pair into hi bf16x2 and residual bf16x2
__device__ __forceinline__ void psplit(float p0, float p1, uint32_t& hi, uint32_t& lo) {
    hi = bf16x2(p0, p1);
    float h0 = __uint_as_float(hi << 16);
    float h1 = __uint_as_float(hi & 0xffff0000u);
    lo = bf16x2(p0 - h0, p1 - h1);
}

// ---------------- GEMM (3xBF16, from R9; mode-0 epilogue now packs) ---------
#define TSTRIDE 36
#define BUF_WORDS (128 * TSTRIDE)
#define BUF_BYTES (BUF_WORDS * 4)
#define GSM_TOTAL (4 * BUF_BYTES)

__global__ __launch_bounds__(256) void gemm_bf16_kernel(
    const uint32_t* __restrict__ A, const uint32_t* __restrict__ Bt,
    float* __restrict__ Of, uint32_t* __restrict__ Opk,
    const float* __restrict__ bias, int mode)
{
    uint32_t* sm = (uint32_t*)dynsm;
    const uint32_t sbase = smem_u32(sm);

    const int tid = threadIdx.x;
    const int m0 = blockIdx.x * 128;
    const int n0 = blockIdx.y * 128;
    const int lane = tid & 31, wid = tid >> 5;
    const int g = lane >> 2, c = lane & 3;
    const int wm = (wid & 1) * 64;
    const int wn = (wid >> 1) * 32;

    const int lrow = tid >> 3;
    const int lch  = tid & 7;
    const uint32_t* Ag = A  + (size_t)(m0 + lrow) * DD + lch * 4;
    const uint32_t* Bg = Bt + (size_t)(n0 + lrow) * DD + lch * 4;

    float d[4][4][4];
#pragma unroll
    for (int mt = 0; mt < 4; mt++)
#pragma unroll
        for (int nt = 0; nt < 4; nt++)
#pragma unroll
            for (int i = 0; i < 4; i++) d[mt][nt][i] = 0.f;

    auto load_tile = [&](int t, int buf) {
        const int k0 = t * 32;
        const uint32_t sa = sbase + buf * BUF_BYTES + (lrow * TSTRIDE + lch * 4) * 4;
        const uint32_t sb = sbase + 2 * BUF_BYTES + buf * BUF_BYTES +
                            (lrow * TSTRIDE + lch * 4) * 4;
#pragma unroll
        for (int r = 0; r < 4; r++) {
            cpa16(sa + r * 32 * TSTRIDE * 4, Ag + (size_t)r * 32 * DD + k0);
            cpa16(sb + r * 32 * TSTRIDE * 4, Bg + (size_t)r * 32 * DD + k0);
        }
    };

    load_tile(0, 0);
    CPA_COMMIT();

    const int NT = DD / 32;
    for (int t = 0; t < NT; t++) {
        const int buf = t & 1;
        if (t + 1 < NT) {
            load_tile(t + 1, (t + 1) & 1);
            CPA_COMMIT();
            CPA_WAIT1();
        } else {
            CPA_WAIT0();
        }
        __syncthreads();

        const uint32_t* as = sm + buf * BUF_WORDS;
        const uint32_t* bs = sm + 2 * BUF_WORDS + buf * BUF_WORDS;
#pragma unroll
        for (int kk = 0; kk < 32; kk += 16) {
            uint32_t ah[4][4], al[4][4], bh[4][2], bl[4][2];
#pragma unroll
            for (int mt = 0; mt < 4; mt++) {
                const int rb = wm + mt * 16 + g;
                uint2 p0 = *(const uint2*)&as[rb * TSTRIDE + kk + 2 * c];
                uint2 p1 = *(const uint2*)&as[(rb + 8) * TSTRIDE + kk + 2 * c];
                uint2 p2 = *(const uint2*)&as[rb * TSTRIDE + kk + 2 * c + 8];
                uint2 p3 = *(const uint2*)&as[(rb + 8) * TSTRIDE + kk + 2 * c + 8];
                ah[mt][0] = __byte_perm(p0.x, p0.y, 0x7632);
                al[mt][0] = __byte_perm(p0.x, p0.y, 0x5410);
                ah[mt][1] = __byte_perm(p1.x, p1.y, 0x7632);
                al[mt][1] = __byte_perm(p1.x, p1.y, 0x5410);
                ah[mt][2] = __byte_perm(p2.x, p2.y, 0x7632);
                al[mt][2] = __byte_perm(p2.x, p2.y, 0x5410);
                ah[mt][3] = __byte_perm(p3.x, p3.y, 0x7632);
                al[mt][3] = __byte_perm(p3.x, p3.y, 0x5410);
            }
#pragma unroll
            for (int nt = 0; nt < 4; nt++) {
                const int nb = wn + nt * 8 + g;
                uint2 q0 = *(const uint2*)&bs[nb * TSTRIDE + kk + 2 * c];
                uint2 q1 = *(const uint2*)&bs[nb * TSTRIDE + kk + 2 * c + 8];
                bh[nt][0] = __byte_perm(q0.x, q0.y, 0x7632);
                bl[nt][0] = __byte_perm(q0.x, q0.y, 0x5410);
                bh[nt][1] = __byte_perm(q1.x, q1.y, 0x7632);
                bl[nt][1] = __byte_perm(q1.x, q1.y, 0x5410);
            }
#pragma unroll
            for (int mt = 0; mt < 4; mt++)
#pragma unroll
                for (int nt = 0; nt < 4; nt++)
                    MMA_BF16(d[mt][nt], ah[mt], bl[nt]);
#pragma unroll
            for (int mt = 0; mt < 4; mt++)
#pragma unroll
                for (int nt = 0; nt < 4; nt++)
                    MMA_BF16(d[mt][nt], al[mt], bh[nt]);
#pragma unroll
            for (int mt = 0; mt < 4; mt++)
#pragma unroll
                for (int nt = 0; nt < 4; nt++)
                    MMA_BF16(d[mt][nt], ah[mt], bh[nt]);
        }
        __syncthreads();
    }

#pragma unroll
    for (int mt = 0; mt < 4; mt++) {
        const int r1 = m0 + wm + mt * 16 + g;
        const int r2 = r1 + 8;
#pragma unroll
        for (int nt = 0; nt < 4; nt++) {
            const int cg = n0 + wn + nt * 8 + c * 2;
            if (mode == 0) {
                const int h = cg >> 6, hn = cg & 63;
                const int b1 = r1 >> 11, s1 = r1 & (SS - 1);
                const int b2 = r2 >> 11, s2 = r2 & (SS - 1);
                uint32_t* p1 = Opk + (((size_t)(b1 * HH + h) * SS + s1) * HD + hn);
                uint32_t* p2 = Opk + (((size_t)(b2 * HH + h) * SS + s2) * HD + hn);
                uint2 w1 = make_uint2(pack_bf16split(d[mt][nt][0]),
                                      pack_bf16split(d[mt][nt][1]));
                uint2 w2 = make_uint2(pack_bf16split(d[mt][nt][2]),
                                      pack_bf16split(d[mt][nt][3]));
                *(uint2*)p1 = w1;
                *(uint2*)p2 = w2;
            } else {
                float2 bb = *(const float2*)(bias + cg);
                *(float2*)(Of + (size_t)r1 * DD + cg) =
                    make_float2(d[mt][nt][0] + bb.x, d[mt][nt][1] + bb.y);
                *(float2*)(Of + (size_t)r2 * DD + cg) =
                    make_float2(d[mt][nt][2] + bb.x, d[mt][nt][3] + bb.y);
            }
        }
    }
}

// ---------------- prepass kernels -------------------------------------------
__global__ void pack_kernel(const float* __restrict__ in, uint32_t* __restrict__ out) {
    int i = (blockIdx.x * 256 + threadIdx.x) * 4;
    float4 v = *(const float4*)(in + i);
    uint4 r;
    r.x = pack_bf16split(v.x);
    r.y = pack_bf16split(v.y);
    r.z = pack_bf16split(v.z);
    r.w = pack_bf16split(v.w);
    *(uint4*)(out + i) = r;
}

__global__ void wtrans_kernel(const float* __restrict__ W, uint32_t* __restrict__ Wt) {
    __shared__ float t[32][33];
    const int h = blockIdx.z, k0 = blockIdx.x * 32, n0 = blockIdx.y * 32;
    const int tx = threadIdx.x, ty = threadIdx.y;
#pragma unroll
    for (int i = ty; i < 32; i += 8)
        t[i][tx] = W[((size_t)h * DD + k0 + i) * HD + n0 + tx];
    __syncthreads();
#pragma unroll
    for (int i = ty; i < 32; i += 8)
        Wt[(size_t)(h * HD + n0 + i) * DD + k0 + tx] = pack_bf16split(t[tx][i]);
}

// ---------------- tensor-core causal flash attention ------------------------
// CTA: 128 q-rows x 64 kv-cols, 8 warps (16 rows each). Q frags in registers.
// K/V smem [64][68] u32 packed, double-buffered.
#define KVSTR 68
#define KV_WORDS (64 * KVSTR)
#define KV_BYTES (KV_WORDS * 4)
#define FSM_TOTAL (4 * KV_BYTES)        // 2xK + 2xV = 69632 B

__global__ __launch_bounds__(256) void flash_mma_kernel(
    const uint32_t* __restrict__ Qp, const uint32_t* __restrict__ Kp,
    const uint32_t* __restrict__ Vp, uint32_t* __restrict__ AO)
{
    uint32_t* sm = (uint32_t*)dynsm;
    const uint32_t sbase = smem_u32(sm);

    const int qi  = (int)gridDim.x - 1 - (int)blockIdx.x;   // heavy tiles first
    const int bh  = blockIdx.y;
    const int b   = bh >> 4, h = bh & 15;
    const int qm0 = qi * 128;

    const uint32_t* Qh = Qp + (size_t)bh * SS * HD;
    const uint32_t* Kh = Kp + (size_t)bh * SS * HD;
    const uint32_t* Vh = Vp + (size_t)bh * SS * HD;

    const int tid = threadIdx.x;
    const int lane = tid & 31, wid = tid >> 5;
    const int g = lane >> 2, c = lane & 3;
    const int wm = wid * 16;

    // ---- Q fragments (hoisted; rows qm0+wm+g and +8) ----
    uint32_t qh[4][4], ql[4][4];
    {
        const uint32_t* q0 = Qh + (size_t)(qm0 + wm + g) * HD;
        const uint32_t* q1 = q0 + 8 * HD;
#pragma unroll
        for (int kx = 0; kx < 4; kx++) {
            const int k0 = kx * 16 + 2 * c;
            uint2 p0 = *(const uint2*)(q0 + k0);
            uint2 p1 = *(const uint2*)(q1 + k0);
            uint2 p2 = *(const uint2*)(q0 + k0 + 8);
            uint2 p3 = *(const uint2*)(q1 + k0 + 8);
            qh[kx][0] = __byte_perm(p0.x, p0.y, 0x7632);
            ql[kx][0] = __byte_perm(p0.x, p0.y, 0x5410);
            qh[kx][1] = __byte_perm(p1.x, p1.y, 0x7632);
            ql[kx][1] = __byte_perm(p1.x, p1.y, 0x5410);
            qh[kx][2] = __byte_perm(p2.x, p2.y, 0x7632);
            ql[kx][2] = __byte_perm(p2.x, p2.y, 0x5410);
            qh[kx][3] = __byte_perm(p3.x, p3.y, 0x7632);
            ql[kx][3] = __byte_perm(p3.x, p3.y, 0x5410);
        }
    }

    float m0r = -1e30f, m1r = -1e30f, l0 = 0.f, l1 = 0.f;
    float o[8][4];
#pragma unroll
    for (int j = 0; j < 8; j++)
#pragma unroll
        for (int i = 0; i < 4; i++) o[j][i] = 0.f;

    auto load_kv = [&](int kt, int buf) {
        const uint32_t* kg = Kh + (size_t)kt * 64 * HD;
        const uint32_t* vg = Vh + (size_t)kt * 64 * HD;
        const uint32_t kdst = sbase + buf * KV_BYTES;
        const uint32_t vdst = sbase + 2 * KV_BYTES + buf * KV_BYTES;
#pragma unroll
        for (int i = 0; i < 4; i++) {
            const int cid = tid + i * 256;          // 0..1023
            const int row = cid >> 4, cc = (cid & 15) * 4;
            cpa16(kdst + (row * KVSTR + cc) * 4, kg + row * HD + cc);
            cpa16(vdst + (row * KVSTR + cc) * 4, vg + row * HD + cc);
        }
    };

    const int nkv = 2 * qi + 2;
    load_kv(0, 0);
    CPA_COMMIT();

    const float SC = 0.18033688f;  // 0.125 * log2(e)

    for (int kt = 0; kt < nkv; kt++) {
        const int buf = kt & 1;
        if (kt + 1 < nkv) {
            load_kv(kt + 1, (kt + 1) & 1);
            CPA_COMMIT();
            CPA_WAIT1();
        } else {
            CPA_WAIT0();
        }
        __syncthreads();

        const uint32_t* ks = sm + buf * KV_WORDS;
        const uint32_t* vs = sm + 2 * KV_WORDS + buf * KV_WORDS;

        // ---- S = Q K^T ----
        float s[8][4];
#pragma unroll
        for (int j = 0; j < 8; j++)
#pragma unroll
            for (int i = 0; i < 4; i++) s[j][i] = 0.f;

#pragma unroll
        for (int kx = 0; kx < 4; kx++) {
#pragma unroll
            for (int j = 0; j < 8; j++) {
                uint2 r0 = *(const uint2*)&ks[(8 * j + g) * KVSTR + kx * 16 + 2 * c];
                uint2 r1 = *(const uint2*)&ks[(8 * j + g) * KVSTR + kx * 16 + 2 * c + 8];
                uint32_t bhf[2], blf[2];
                bhf[0] = __byte_perm(r0.x, r0.y, 0x7632);
                blf[0] = __byte_perm(r0.x, r0.y, 0x5410);
                bhf[1] = __byte_perm(r1.x, r1.y, 0x7632);
                blf[1] = __byte_perm(r1.x, r1.y, 0x5410);
                MMA_BF16(s[j], qh[kx], blf);
                MMA_BF16(s[j], ql[kx], bhf);
                MMA_BF16(s[j], qh[kx], bhf);
            }
        }

        // ---- causal mask (last two tiles only) ----
        if (kt >= nkv - 2) {
            const int row0 = qm0 + wm + g, row1 = row0 + 8;
            const int cb = kt * 64 + 2 * c;
#pragma unroll
            for (int j = 0; j < 8; j++) {
                const int c0 = cb + 8 * j;
                if (c0 > row0)     s[j][0] = -1e30f;
                if (c0 + 1 > row0) s[j][1] = -1e30f;
                if (c0 > row1)     s[j][2] = -1e30f;
                if (c0 + 1 > row1) s[j][3] = -1e30f;
            }
        }

        // ---- online softmax (row groups = 4 lanes) ----
        float mx0 = -1e30f, mx1 = -1e30f;
#pragma unroll
        for (int j = 0; j < 8; j++) {
            mx0 = fmaxf(mx0, fmaxf(s[j][0], s[j][1]));
            mx1 = fmaxf(mx1, fmaxf(s[j][2], s[j][3]));
        }
        mx0 = fmaxf(mx0, __shfl_xor_sync(0xffffffffu, mx0, 1));
        mx0 = fmaxf(mx0, __shfl_xor_sync(0xffffffffu, mx0, 2));
        mx1 = fmaxf(mx1, __shfl_xor_sync(0xffffffffu, mx1, 1));
        mx1 = fmaxf(mx1, __shfl_xor_sync(0xffffffffu, mx1, 2));

        const float mn0 = fmaxf(m0r, mx0), mn1 = fmaxf(m1r, mx1);
        const float al0 = exp2f((m0r - mn0) * SC);
        const float al1 = exp2f((m1r - mn1) * SC);
        m0r = mn0; m1r = mn1;

        float rs0 = 0.f, rs1 = 0.f;
#pragma unroll
        for (int j = 0; j < 8; j++) {
            s[j][0] = exp2f((s[j][0] - mn0) * SC);
            s[j][1] = exp2f((s[j][1] - mn0) * SC);
            s[j][2] = exp2f((s[j][2] - mn1) * SC);
            s[j][3] = exp2f((s[j][3] - mn1) * SC);
            rs0 += s[j][0] + s[j][1];
            rs1 += s[j][2] + s[j][3];
        }
        rs0 += __shfl_xor_sync(0xffffffffu, rs0, 1);
        rs0 += __shfl_xor_sync(0xffffffffu, rs0, 2);
        rs1 += __shfl_xor_sync(0xffffffffu, rs1, 1);
        rs1 += __shfl_xor_sync(0xffffffffu, rs1, 2);
        l0 = l0 * al0 + rs0;
        l1 = l1 * al1 + rs1;
#pragma unroll
        for (int j = 0; j < 8; j++) {
            o[j][0] *= al0; o[j][1] *= al0;
            o[j][2] *= al1; o[j][3] *= al1;
        }

        // ---- O += P V  (P from S frags, no smem round trip) ----
#pragma unroll
        for (int j2 = 0; j2 < 4; j2++) {
            uint32_t ph[4], pl[4];
            psplit(s[2 * j2][0],     s[2 * j2][1],     ph[0], pl[0]);
            psplit(s[2 * j2][2],     s[2 * j2][3],     ph[1], pl[1]);
            psplit(s[2 * j2 + 1][0], s[2 * j2 + 1][1], ph[2], pl[2]);
            psplit(s[2 * j2 + 1][2], s[2 * j2 + 1][3], ph[3], pl[3]);
            const int t0 = 16 * j2 + 2 * c;
#pragma unroll
            for (int jo = 0; jo < 8; jo++) {
                const int dv = 8 * jo + g;
                uint32_t v00 = vs[t0 * KVSTR + dv];
                uint32_t v01 = vs[(t0 + 1) * KVSTR + dv];
                uint32_t v10 = vs[(t0 + 8) * KVSTR + dv];
                uint32_t v11 = vs[(t0 + 9) * KVSTR + dv];
                uint32_t bhf[2], blf[2];
                bhf[0] = __byte_perm(v00, v01, 0x7632);
                blf[0] = __byte_perm(v00, v01, 0x5410);
                bhf[1] = __byte_perm(v10, v11, 0x7632);
                blf[1] = __byte_perm(v10, v11, 0x5410);
                MMA_BF16(o[jo], ph, blf);
                MMA_BF16(o[jo], pl, bhf);
                MMA_BF16(o[jo], ph, bhf);
            }
        }
        __syncthreads();   // all reads of this buffer done before next cp.async
    }

    // ---- epilogue: normalize + packed store ----
    const float inv0 = 1.f / l0, inv1 = 1.f / l1;
    const int s0 = qm0 + wm + g, s1 = s0 + 8;
    uint32_t* a0 = AO + ((size_t)b * SS + s0) * DD + h * HD;
    uint32_t* a1 = AO + ((size_t)b * SS + s1) * DD + h * HD;
#pragma unroll
    for (int j = 0; j < 8; j++) {
        uint2 w0 = make_uint2(pack_bf16split(o[j][0] * inv0),
                              pack_bf16split(o[j][1] * inv0));
        uint2 w1 = make_uint2(pack_bf16split(o[j][2] * inv1),
                              pack_bf16split(o[j][3] * inv1));
        *(uint2*)&a0[8 * j + 2 * c] = w0;
        *(uint2*)&a1[8 * j + 2 * c] = w1;
    }
}

// ---------------------------------------------------------------------------
extern "C" void kernel_launch(void* const* d_in, const int* in_sizes, int n_in,
                              void* d_out, int out_size) {
    const float* q  = (const float*)d_in[0];
    const float* k  = (const float*)d_in[1];
    const float* v  = (const float*)d_in[2];
    const float* Wq = (const float*)d_in[3];
    const float* Wk = (const float*)d_in[4];
    const float* Wv = (const float*)d_in[5];
    const float* Wo = (const float*)d_in[6];
    const float* bo = (const float*)d_in[7];
    float* out = (float*)d_out;

    uint32_t *Qpp, *Kpp, *Vpp, *AOp, *Pq, *Pk, *Pv, *Wqt, *Wkt, *Wvt, *Wot;
    cudaGetSymbolAddress((void**)&Qpp, g_Qp);
    cudaGetSymbolAddress((void**)&Kpp, g_Kp);
    cudaGetSymbolAddress((void**)&Vpp, g_Vp);
    cudaGetSymbolAddress((void**)&AOp, g_AO);
    cudaGetSymbolAddress((void**)&Pq, g_Pq);
    cudaGetSymbolAddress((void**)&Pk, g_Pk);
    cudaGetSymbolAddress((void**)&Pv, g_Pv);
    cudaGetSymbolAddress((void**)&Wqt, g_Wqt);
    cudaGetSymbolAddress((void**)&Wkt, g_Wkt);
    cudaGetSymbolAddress((void**)&Wvt, g_Wvt);
    cudaGetSymbolAddress((void**)&Wot, g_Wot);

    const int M = BB * SS;                 // 8192
    const int NELEM = M * DD;

    pack_kernel<<<NELEM / 1024, 256>>>(q, Pq);
    pack_kernel<<<NELEM / 1024, 256>>>(k, Pk);
    pack_kernel<<<NELEM / 1024, 256>>>(v, Pv);
    pack_kernel<<<DD * DD / 1024, 256>>>(Wo, Wot);
    dim3 tb(32, 8);
    dim3 tg(DD / 32, HD / 32, HH);
    wtrans_kernel<<<tg, tb>>>(Wq, Wqt);
    wtrans_kernel<<<tg, tb>>>(Wk, Wkt);
    wtrans_kernel<<<tg, tb>>>(Wv, Wvt);

    cudaFuncSetAttribute(gemm_bf16_kernel,
                         cudaFuncAttributeMaxDynamicSharedMemorySize, GSM_TOTAL);
    cudaFuncSetAttribute(flash_mma_kernel,
                         cudaFuncAttributeMaxDynamicSharedMemorySize, FSM_TOTAL);

    dim3 gg(M / 128, DD / 128);
    gemm_bf16_kernel<<<gg, 256, GSM_TOTAL>>>(Pq, Wqt, nullptr, Qpp, bo, 0);
    gemm_bf16_kernel<<<gg, 256, GSM_TOTAL>>>(Pk, Wkt, nullptr, Kpp, bo, 0);
    gemm_bf16_kernel<<<gg, 256, GSM_TOTAL>>>(Pv, Wvt, nullptr, Vpp, bo, 0);

    flash_mma_kernel<<<dim3(SS / 128, BB * HH), 256, FSM_TOTAL>>>(Qpp, Kpp, Vpp, AOp);

    gemm_bf16_kernel<<<gg, 256, GSM_TOTAL>>>(AOp, Wot, out, nullptr, bo, 1);
}

// round 14
// speedup vs baseline: 3.6841x; 1.0094x over previous
#include <cuda_runtime.h>
#include <cuda_fp16.h>
#include <math.h>
#include <stdint.h>

#define BB 4
#define SS 2048
#define DD 1024
#define HH 16
#define HD 64

// ---------------- scratch (device globals; no allocations allowed) ----------
__device__ uint32_t g_Qp[(size_t)BB * HH * SS * HD];  // [B,H,S,64] packed fp16 hi|lo
__device__ uint32_t g_Kp[(size_t)BB * HH * SS * HD];
__device__ uint32_t g_Vp[(size_t)BB * HH * SS * HD];
__device__ uint32_t g_AO[(size_t)BB * SS * DD];       // [B,S,H*64] packed
__device__ uint32_t g_Pq[(size_t)BB * SS * DD];       // packed inputs
__device__ uint32_t g_Pk[(size_t)BB * SS * DD];
__device__ uint32_t g_Pv[(size_t)BB * SS * DD];
__device__ uint32_t g_Wqt[(size_t)DD * DD];           // [h*64+n][k] packed
__device__ uint32_t g_Wkt[(size_t)DD * DD];
__device__ uint32_t g_Wvt[(size_t)DD * DD];
__device__ uint32_t g_Wot[(size_t)DD * DD];           // [n][k] packed

extern __shared__ char dynsm[];

// ---------------- helpers ---------------------------------------------------
__device__ __forceinline__ uint32_t smem_u32(const void* p) {
    uint32_t a;
    asm("{ .reg .u64 t; cvta.to.shared.u64 t, %1; cvt.u32.u64 %0, t; }"
        : "=r"(a) : "l"(p));
    return a;
}
__device__ __forceinline__ void cpa16(uint32_t dst, const void* src) {
    asm volatile("cp.async.cg.shared.global [%0], [%1], 16;" :: "r"(dst), "l"(src));
}
#define CPA_COMMIT() asm volatile("cp.async.commit_group;" ::: "memory")
#define CPA_WAIT1()  asm volatile("cp.async.wait_group 1;" ::: "memory")
#define CPA_WAIT0()  asm volatile("cp.async.wait_group 0;" ::: "memory")

#define MMA_F16(d, a, b)                                                       \
    asm volatile("mma.sync.aligned.m16n8k16.row.col.f32.f16.f16.f32 "          \
        "{%0,%1,%2,%3}, {%4,%5,%6,%7}, {%8,%9}, {%0,%1,%2,%3};"                \
        : "+f"((d)[0]), "+f"((d)[1]), "+f"((d)[2]), "+f"((d)[3])               \
        : "r"((a)[0]), "r"((a)[1]), "r"((a)[2]), "r"((a)[3]),                  \
          "r"((b)[0]), "r"((b)[1]))

// pack f32 -> (f16_hi << 16) | f16_lo ; hi = rn(x), lo = rn(x - hi)
__device__ __forceinline__ uint32_t pack_f16split(float x) {
    __half h = __float2half_rn(x);
    __half l = __float2half_rn(x - __half2float(h));
    return ((uint32_t)__half_as_ushort(h) << 16) | (uint32_t)__half_as_ushort(l);
}
// split a pair into hi f16x2 and residual f16x2 (low half = first arg)
__device__ __forceinline__ void psplit(float p0, float p1, uint32_t& hi, uint32_t& lo) {
    __half h0 = __float2half_rn(p0), h1 = __float2half_rn(p1);
    hi = ((uint32_t)__half_as_ushort(h1) << 16) | (uint32_t)__half_as_ushort(h0);
    __half l0 = __float2half_rn(p0 - __half2float(h0));
    __half l1 = __float2half_rn(p1 - __half2float(h1));
    lo = ((uint32_t)__half_as_ushort(l1) << 16) | (uint32_t)__half_as_ushort(l0);
}

// ---------------- GEMM (2-term fp16: a_hi*(b_hi+b_lo)) ----------------------
#define TSTRIDE 36
#define BUF_WORDS (128 * TSTRIDE)
#define BUF_BYTES (BUF_WORDS * 4)
#define GSM_TOTAL (4 * BUF_BYTES)

__global__ __launch_bounds__(256) void gemm_f16_kernel(
    const uint32_t* __restrict__ A, const uint32_t* __restrict__ Bt,
    float* __restrict__ Of, uint32_t* __restrict__ Opk,
    const float* __restrict__ bias, int mode)
{
    uint32_t* sm = (uint32_t*)dynsm;
    const uint32_t sbase = smem_u32(sm);

    const int tid = threadIdx.x;
    const int m0 = blockIdx.x * 128;
    const int n0 = blockIdx.y * 128;
    const int lane = tid & 31, wid = tid >> 5;
    const int g = lane >> 2, c = lane & 3;
    const int wm = (wid & 1) * 64;
    const int wn = (wid >> 1) * 32;

    const int lrow = tid >> 3;
    const int lch  = tid & 7;
    const uint32_t* Ag = A  + (size_t)(m0 + lrow) * DD + lch * 4;
    const uint32_t* Bg = Bt + (size_t)(n0 + lrow) * DD + lch * 4;

    float d[4][4][4];
#pragma unroll
    for (int mt = 0; mt < 4; mt++)
#pragma unroll
        for (int nt = 0; nt < 4; nt++)
#pragma unroll
            for (int i = 0; i < 4; i++) d[mt][nt][i] = 0.f;

    auto load_tile = [&](int t, int buf) {
        const int k0 = t * 32;
        const uint32_t sa = sbase + buf * BUF_BYTES + (lrow * TSTRIDE + lch * 4) * 4;
        const uint32_t sb = sbase + 2 * BUF_BYTES + buf * BUF_BYTES +
                            (lrow * TSTRIDE + lch * 4) * 4;
#pragma unroll
        for (int r = 0; r < 4; r++) {
            cpa16(sa + r * 32 * TSTRIDE * 4, Ag + (size_t)r * 32 * DD + k0);
            cpa16(sb + r * 32 * TSTRIDE * 4, Bg + (size_t)r * 32 * DD + k0);
        }
    };

    load_tile(0, 0);
    CPA_COMMIT();

    const int NT = DD / 32;
    for (int t = 0; t < NT; t++) {
        const int buf = t & 1;
        if (t + 1 < NT) {
            load_tile(t + 1, (t + 1) & 1);
            CPA_COMMIT();
            CPA_WAIT1();
        } else {
            CPA_WAIT0();
        }
        __syncthreads();

        const uint32_t* as = sm + buf * BUF_WORDS;
        const uint32_t* bs = sm + 2 * BUF_WORDS + buf * BUF_WORDS;
#pragma unroll
        for (int kk = 0; kk < 32; kk += 16) {
            uint32_t ah[4][4], bh[4][2], bl[4][2];
#pragma unroll
            for (int mt = 0; mt < 4; mt++) {
                const int rb = wm + mt * 16 + g;
                uint2 p0 = *(const uint2*)&as[rb * TSTRIDE + kk + 2 * c];
                uint2 p1 = *(const uint2*)&as[(rb + 8) * TSTRIDE + kk + 2 * c];
                uint2 p2 = *(const uint2*)&as[rb * TSTRIDE + kk + 2 * c + 8];
                uint2 p3 = *(const uint2*)&as[(rb + 8) * TSTRIDE + kk + 2 * c + 8];
                ah[mt][0] = __byte_perm(p0.x, p0.y, 0x7632);
                ah[mt][1] = __byte_perm(p1.x, p1.y, 0x7632);
                ah[mt][2] = __byte_perm(p2.x, p2.y, 0x7632);
                ah[mt][3] = __byte_perm(p3.x, p3.y, 0x7632);
            }
#pragma unroll
            for (int nt = 0; nt < 4; nt++) {
                const int nb = wn + nt * 8 + g;
                uint2 q0 = *(const uint2*)&bs[nb * TSTRIDE + kk + 2 * c];
                uint2 q1 = *(const uint2*)&bs[nb * TSTRIDE + kk + 2 * c + 8];
                bh[nt][0] = __byte_perm(q0.x, q0.y, 0x7632);
                bl[nt][0] = __byte_perm(q0.x, q0.y, 0x5410);
                bh[nt][1] = __byte_perm(q1.x, q1.y, 0x7632);
                bl[nt][1] = __byte_perm(q1.x, q1.y, 0x5410);
            }
#pragma unroll
            for (int mt = 0; mt < 4; mt++)
#pragma unroll
                for (int nt = 0; nt < 4; nt++)
                    MMA_F16(d[mt][nt], ah[mt], bl[nt]);
#pragma unroll
            for (int mt = 0; mt < 4; mt++)
#pragma unroll
                for (int nt = 0; nt < 4; nt++)
                    MMA_F16(d[mt][nt], ah[mt], bh[nt]);
        }
        __syncthreads();
    }

#pragma unroll
    for (int mt = 0; mt < 4; mt++) {
        const int r1 = m0 + wm + mt * 16 + g;
        const int r2 = r1 + 8;
#pragma unroll
        for (int nt = 0; nt < 4; nt++) {
            const int cg = n0 + wn + nt * 8 + c * 2;
            if (mode == 0) {
                const int h = cg >> 6, hn = cg & 63;
                const int b1 = r1 >> 11, s1 = r1 & (SS - 1);
                const int b2 = r2 >> 11, s2 = r2 & (SS - 1);
                uint32_t* p1 = Opk + (((size_t)(b1 * HH + h) * SS + s1) * HD + hn);
                uint32_t* p2 = Opk + (((size_t)(b2 * HH + h) * SS + s2) * HD + hn);
                uint2 w1 = make_uint2(pack_f16split(d[mt][nt][0]),
                                      pack_f16split(d[mt][nt][1]));
                uint2 w2 = make_uint2(pack_f16split(d[mt][nt][2]),
                                      pack_f16split(d[mt][nt][3]));
                *(uint2*)p1 = w1;
                *(uint2*)p2 = w2;
            } else {
                float2 bb = *(const float2*)(bias + cg);
                *(float2*)(Of + (size_t)r1 * DD + cg) =
                    make_float2(d[mt][nt][0] + bb.x, d[mt][nt][1] + bb.y);
                *(float2*)(Of + (size_t)r2 * DD + cg) =
                    make_float2(d[mt][nt][2] + bb.x, d[mt][nt][3] + bb.y);
            }
        }
    }
}

// ---------------- prepass kernels -------------------------------------------
__global__ void pack_kernel(const float* __restrict__ in, uint32_t* __restrict__ out) {
    int i = (blockIdx.x * 256 + threadIdx.x) * 4;
    float4 v = *(const float4*)(in + i);
    uint4 r;
    r.x = pack_f16split(v.x);
    r.y = pack_f16split(v.y);
    r.z = pack_f16split(v.z);
    r.w = pack_f16split(v.w);
    *(uint4*)(out + i) = r;
}

__global__ void wtrans_kernel(const float* __restrict__ W, uint32_t* __restrict__ Wt) {
    __shared__ float t[32][33];
    const int h = blockIdx.z, k0 = blockIdx.x * 32, n0 = blockIdx.y * 32;
    const int tx = threadIdx.x, ty = threadIdx.y;
#pragma unroll
    for (int i = ty; i < 32; i += 8)
        t[i][tx] = W[((size_t)h * DD + k0 + i) * HD + n0 + tx];
    __syncthreads();
#pragma unroll
    for (int i = ty; i < 32; i += 8)
        Wt[(size_t)(h * HD + n0 + i) * DD + k0 + tx] = pack_f16split(t[tx][i]);
}

// ---------------- tensor-core causal flash attention (3-term fp16) ----------
#define KVSTR 68
#define KV_WORDS (64 * KVSTR)
#define KV_BYTES (KV_WORDS * 4)
#define FSM_TOTAL (4 * KV_BYTES)

__global__ __launch_bounds__(256) void flash_mma_kernel(
    const uint32_t* __restrict__ Qp, const uint32_t* __restrict__ Kp,
    const uint32_t* __restrict__ Vp, uint32_t* __restrict__ AO)
{
    uint32_t* sm = (uint32_t*)dynsm;
    const uint32_t sbase = smem_u32(sm);

    const int qi  = (int)gridDim.x - 1 - (int)blockIdx.x;
    const int bh  = blockIdx.y;
    const int b   = bh >> 4, h = bh & 15;
    const int qm0 = qi * 128;

    const uint32_t* Qh = Qp + (size_t)bh * SS * HD;
    const uint32_t* Kh = Kp + (size_t)bh * SS * HD;
    const uint32_t* Vh = Vp + (size_t)bh * SS * HD;

    const int tid = threadIdx.x;
    const int lane = tid & 31, wid = tid >> 5;
    const int g = lane >> 2, c = lane & 3;
    const int wm = wid * 16;

    uint32_t qh[4][4], ql[4][4];
    {
        const uint32_t* q0 = Qh + (size_t)(qm0 + wm + g) * HD;
        const uint32_t* q1 = q0 + 8 * HD;
#pragma unroll
        for (int kx = 0; kx < 4; kx++) {
            const int k0 = kx * 16 + 2 * c;
            uint2 p0 = *(const uint2*)(q0 + k0);
            uint2 p1 = *(const uint2*)(q1 + k0);
            uint2 p2 = *(const uint2*)(q0 + k0 + 8);
            uint2 p3 = *(const uint2*)(q1 + k0 + 8);
            qh[kx][0] = __byte_perm(p0.x, p0.y, 0x7632);
            ql[kx][0] = __byte_perm(p0.x, p0.y, 0x5410);
            qh[kx][1] = __byte_perm(p1.x, p1.y, 0x7632);
            ql[kx][1] = __byte_perm(p1.x, p1.y, 0x5410);
            qh[kx][2] = __byte_perm(p2.x, p2.y, 0x7632);
            ql[kx][2] = __byte_perm(p2.x, p2.y, 0x5410);
            qh[kx][3] = __byte_perm(p3.x, p3.y, 0x7632);
            ql[kx][3] = __byte_perm(p3.x, p3.y, 0x5410);
        }
    }

    float m0r = -1e30f, m1r = -1e30f, l0 = 0.f, l1 = 0.f;
    float o[8][4];
#pragma unroll
    for (int j = 0; j < 8; j++)
#pragma unroll
        for (int i = 0; i < 4; i++) o[j][i] = 0.f;

    auto load_kv = [&](int kt, int buf) {
        const uint32_t* kg = Kh + (size_t)kt * 64 * HD;
        const uint32_t* vg = Vh + (size_t)kt * 64 * HD;
        const uint32_t kdst = sbase + buf * KV_BYTES;
        const uint32_t vdst = sbase + 2 * KV_BYTES + buf * KV_BYTES;
#pragma unroll
        for (int i = 0; i < 4; i++) {
            const int cid = tid + i * 256;
            const int row = cid >> 4, cc = (cid & 15) * 4;
            cpa16(kdst + (row * KVSTR + cc) * 4, kg + row * HD + cc);
            cpa16(vdst + (row * KVSTR + cc) * 4, vg + row * HD + cc);
        }
    };

    const int nkv = 2 * qi + 2;
    load_kv(0, 0);
    CPA_COMMIT();

    const float SC = 0.18033688f;  // 0.125 * log2(e)

    for (int kt = 0; kt < nkv; kt++) {
        const int buf = kt & 1;
        if (kt + 1 < nkv) {
            load_kv(kt + 1, (kt + 1) & 1);
            CPA_COMMIT();
            CPA_WAIT1();
        } else {
            CPA_WAIT0();
        }
        __syncthreads();

        const uint32_t* ks = sm + buf * KV_WORDS;
        const uint32_t* vs = sm + 2 * KV_WORDS + buf * KV_WORDS;

        float s[8][4];
#pragma unroll
        for (int j = 0; j < 8; j++)
#pragma unroll
            for (int i = 0; i < 4; i++) s[j][i] = 0.f;

#pragma unroll
        for (int kx = 0; kx < 4; kx++) {
#pragma unroll
            for (int j = 0; j < 8; j++) {
                uint2 r0 = *(const uint2*)&ks[(8 * j + g) * KVSTR + kx * 16 + 2 * c];
                uint2 r1 = *(const uint2*)&ks[(8 * j + g) * KVSTR + kx * 16 + 2 * c + 8];
                uint32_t bhf[2], blf[2];
                bhf[0] = __byte_perm(r0.x, r0.y, 0x7632);
                blf[0] = __byte_perm(r0.x, r0.y, 0x5410);
                bhf[1] = __byte_perm(r1.x, r1.y, 0x7632);
                blf[1] = __byte_perm(r1.x, r1.y, 0x5410);
                MMA_F16(s[j], qh[kx], blf);
                MMA_F16(s[j], ql[kx], bhf);
                MMA_F16(s[j], qh[kx], bhf);
            }
        }

        if (kt >= nkv - 2) {
            const int row0 = qm0 + wm + g, row1 = row0 + 8;
            const int cb = kt * 64 + 2 * c;
#pragma unroll
            for (int j = 0; j < 8; j++) {
                const int c0 = cb + 8 * j;
                if (c0 > row0)     s[j][0] = -1e30f;
                if (c0 + 1 > row0) s[j][1] = -1e30f;
                if (c0 > row1)     s[j][2] = -1e30f;
                if (c0 + 1 > row1) s[j][3] = -1e30f;
            }
        }

        float mx0 = -1e30f, mx1 = -1e30f;
#pragma unroll
        for (int j = 0; j < 8; j++) {
            mx0 = fmaxf(mx0, fmaxf(s[j][0], s[j][1]));
            mx1 = fmaxf(mx1, fmaxf(s[j][2], s[j][3]));
        }
        mx0 = fmaxf(mx0, __shfl_xor_sync(0xffffffffu, mx0, 1));
        mx0 = fmaxf(mx0, __shfl_xor_sync(0xffffffffu, mx0, 2));
        mx1 = fmaxf(mx1, __shfl_xor_sync(0xffffffffu, mx1, 1));
        mx1 = fmaxf(mx1, __shfl_xor_sync(0xffffffffu, mx1, 2));

        const float mn0 = fmaxf(m0r, mx0), mn1 = fmaxf(m1r, mx1);
        const float al0 = exp2f((m0r - mn0) * SC);
        const float al1 = exp2f((m1r - mn1) * SC);
        m0r = mn0; m1r = mn1;

        float rs0 = 0.f, rs1 = 0.f;
#pragma unroll
        for (int j = 0; j < 8; j++) {
            s[j][0] = exp2f((s[j][0] - mn0) * SC);
            s[j][1] = exp2f((s[j][1] - mn0) * SC);
            s[j][2] = exp2f((s[j][2] - mn1) * SC);
            s[j][3] = exp2f((s[j][3] - mn1) * SC);
            rs0 += s[j][0] + s[j][1];
            rs1 += s[j][2] + s[j][3];
        }
        rs0 += __shfl_xor_sync(0xffffffffu, rs0, 1);
        rs0 += __shfl_xor_sync(0xffffffffu, rs0, 2);
        rs1 += __shfl_xor_sync(0xffffffffu, rs1, 1);
        rs1 += __shfl_xor_sync(0xffffffffu, rs1, 2);
        l0 = l0 * al0 + rs0;
        l1 = l1 * al1 + rs1;
#pragma unroll
        for (int j = 0; j < 8; j++) {
            o[j][0] *= al0; o[j][1] *= al0;
            o[j][2] *= al1; o[j][3] *= al1;
        }

#pragma unroll
        for (int j2 = 0; j2 < 4; j2++) {
            uint32_t ph[4], pl[4];
            psplit(s[2 * j2][0],     s[2 * j2][1],     ph[0], pl[0]);
            psplit(s[2 * j2][2],     s[2 * j2][3],     ph[1], pl[1]);
            psplit(s[2 * j2 + 1][0], s[2 * j2 + 1][1], ph[2], pl[2]);
            psplit(s[2 * j2 + 1][2], s[2 * j2 + 1][3], ph[3], pl[3]);
            const int t0 = 16 * j2 + 2 * c;
#pragma unroll
            for (int jo = 0; jo < 8; jo++) {
                const int dv = 8 * jo + g;
                uint32_t v00 = vs[t0 * KVSTR + dv];
                uint32_t v01 = vs[(t0 + 1) * KVSTR + dv];
                uint32_t v10 = vs[(t0 + 8) * KVSTR + dv];
                uint32_t v11 = vs[(t0 + 9) * KVSTR + dv];
                uint32_t bhf[2], blf[2];
                bhf[0] = __byte_perm(v00, v01, 0x7632);
                blf[0] = __byte_perm(v00, v01, 0x5410);
                bhf[1] = __byte_perm(v10, v11, 0x7632);
                blf[1] = __byte_perm(v10, v11, 0x5410);
                MMA_F16(o[jo], ph, blf);
                MMA_F16(o[jo], pl, bhf);
                MMA_F16(o[jo], ph, bhf);
            }
        }
        __syncthreads();
    }

    const float inv0 = 1.f / l0, inv1 = 1.f / l1;
    const int s0 = qm0 + wm + g, s1 = s0 + 8;
    uint32_t* a0 = AO + ((size_t)b * SS + s0) * DD + h * HD;
    uint32_t* a1 = AO + ((size_t)b * SS + s1) * DD + h * HD;
#pragma unroll
    for (int j = 0; j < 8; j++) {
        uint2 w0 = make_uint2(pack_f16split(o[j][0] * inv0),
                              pack_f16split(o[j][1] * inv0));
        uint2 w1 = make_uint2(pack_f16split(o[j][2] * inv1),
                              pack_f16split(o[j][3] * inv1));
        *(uint2*)&a0[8 * j + 2 * c] = w0;
        *(uint2*)&a1[8 * j + 2 * c] = w1;
    }
}

// ---------------------------------------------------------------------------
extern "C" void kernel_launch(void* const* d_in, const int* in_sizes, int n_in,
                              void* d_out, int out_size) {
    const float* q  = (const float*)d_in[0];
    const float* k  = (const float*)d_in[1];
    const float* v  = (const float*)d_in[2];
    const float* Wq = (const float*)d_in[3];
    const float* Wk = (const float*)d_in[4];
    const float* Wv = (const float*)d_in[5];
    const float* Wo = (const float*)d_in[6];
    const float* bo = (const float*)d_in[7];
    float* out = (float*)d_out;

    uint32_t *Qpp, *Kpp, *Vpp, *AOp, *Pq, *Pk, *Pv, *Wqt, *Wkt, *Wvt, *Wot;
    cudaGetSymbolAddress((void**)&Qpp, g_Qp);
    cudaGetSymbolAddress((void**)&Kpp, g_Kp);
    cudaGetSymbolAddress((void**)&Vpp, g_Vp);
    cudaGetSymbolAddress((void**)&AOp, g_AO);
    cudaGetSymbolAddress((void**)&Pq, g_Pq);
    cudaGetSymbolAddress((void**)&Pk, g_Pk);
    cudaGetSymbolAddress((void**)&Pv, g_Pv);
    cudaGetSymbolAddress((void**)&Wqt, g_Wqt);
    cudaGetSymbolAddress((void**)&Wkt, g_Wkt);
    cudaGetSymbolAddress((void**)&Wvt, g_Wvt);
    cudaGetSymbolAddress((void**)&Wot, g_Wot);

    const int M = BB * SS;
    const int NELEM = M * DD;

    pack_kernel<<<NELEM / 1024, 256>>>(q, Pq);
    pack_kernel<<<NELEM / 1024, 256>>>(k, Pk);
    pack_kernel<<<NELEM / 1024, 256>>>(v, Pv);
    pack_kernel<<<DD * DD / 1024, 256>>>(Wo, Wot);
    dim3 tb(32, 8);
    dim3 tg(DD / 32, HD / 32, HH);
    wtrans_kernel<<<tg, tb>>>(Wq, Wqt);
    wtrans_kernel<<<tg, tb>>>(Wk, Wkt);
    wtrans_kernel<<<tg, tb>>>(Wv, Wvt);

    cudaFuncSetAttribute(gemm_f16_kernel,
                         cudaFuncAttributeMaxDynamicSharedMemorySize, GSM_TOTAL);
    cudaFuncSetAttribute(flash_mma_kernel,
                         cudaFuncAttributeMaxDynamicSharedMemorySize, FSM_TOTAL);

    dim3 gg(M / 128, DD / 128);
    gemm_f16_kernel<<<gg, 256, GSM_TOTAL>>>(Pq, Wqt, nullptr, Qpp, bo, 0);
    gemm_f16_kernel<<<gg, 256, GSM_TOTAL>>>(Pk, Wkt, nullptr, Kpp, bo, 0);
    gemm_f16_kernel<<<gg, 256, GSM_TOTAL>>>(Pv, Wvt, nullptr, Vpp, bo, 0);

    flash_mma_kernel<<<dim3(SS / 128, BB * HH), 256, FSM_TOTAL>>>(Qpp, Kpp, Vpp, AOp);

    gemm_f16_kernel<<<gg, 256, GSM_TOTAL>>>(AOp, Wot, out, nullptr, bo, 1);
}

// round 15
// speedup vs baseline: 4.7932x; 1.3010x over previous
#include <cuda_runtime.h>
#include <cuda_fp16.h>
#include <math.h>
#include <stdint.h>

#define BB 4
#define SS 2048
#define DD 1024
#define DD2 512
#define HH 16
#define HD 64
#define HD2 32

// ---------------- scratch (device globals; no allocations allowed) ----------
__device__ uint32_t g_Qhi[(size_t)BB * HH * SS * HD2];  // f16x2 d-pair planes
__device__ uint32_t g_Qlo[(size_t)BB * HH * SS * HD2];
__device__ uint32_t g_Khi[(size_t)BB * HH * SS * HD2];
__device__ uint32_t g_Klo[(size_t)BB * HH * SS * HD2];
__device__ uint32_t g_Vp[(size_t)BB * HH * SS * HD];    // old per-elem hi|lo pack
__device__ uint32_t g_AOhi[(size_t)BB * SS * DD2];      // flash out, hi plane
__device__ uint32_t g_Pq[(size_t)BB * SS * DD2];        // input activations, hi plane
__device__ uint32_t g_Pk[(size_t)BB * SS * DD2];
__device__ uint32_t g_Pv[(size_t)BB * SS * DD2];
__device__ uint32_t g_Wqhi[(size_t)DD * DD2], g_Wqlo[(size_t)DD * DD2];
__device__ uint32_t g_Wkhi[(size_t)DD * DD2], g_Wklo[(size_t)DD * DD2];
__device__ uint32_t g_Wvhi[(size_t)DD * DD2], g_Wvlo[(size_t)DD * DD2];
__device__ uint32_t g_Wohi[(size_t)DD * DD2], g_Wolo[(size_t)DD * DD2];

extern __shared__ char dynsm[];

// ---------------- helpers ---------------------------------------------------
__device__ __forceinline__ uint32_t smem_u32(const void* p) {
    uint32_t a;
    asm("{ .reg .u64 t; cvta.to.shared.u64 t, %1; cvt.u32.u64 %0, t; }"
        : "=r"(a) : "l"(p));
    return a;
}
__device__ __forceinline__ void cpa16(uint32_t dst, const void* src) {
    asm volatile("cp.async.cg.shared.global [%0], [%1], 16;" :: "r"(dst), "l"(src));
}
#define CPA_COMMIT() asm volatile("cp.async.commit_group;" ::: "memory")
#define CPA_WAIT1()  asm volatile("cp.async.wait_group 1;" ::: "memory")
#define CPA_WAIT0()  asm volatile("cp.async.wait_group 0;" ::: "memory")

#define MMA_F16(d, a, b)                                                       \
    asm volatile("mma.sync.aligned.m16n8k16.row.col.f32.f16.f16.f32 "          \
        "{%0,%1,%2,%3}, {%4,%5,%6,%7}, {%8,%9}, {%0,%1,%2,%3};"                \
        : "+f"((d)[0]), "+f"((d)[1]), "+f"((d)[2]), "+f"((d)[3])               \
        : "r"((a)[0]), "r"((a)[1]), "r"((a)[2]), "r"((a)[3]),                  \
          "r"((b)[0]), "r"((b)[1]))

// packed f16x2: low half = p0
__device__ __forceinline__ uint32_t cvt_f16x2(float p0, float p1) {
    uint32_t r;
    asm("cvt.rn.f16x2.f32 %0, %1, %2;" : "=r"(r) : "f"(p1), "f"(p0));
    return r;
}
// split a pair into hi f16x2 and residual f16x2
__device__ __forceinline__ void psplit(float p0, float p1, uint32_t& hi, uint32_t& lo) {
    hi = cvt_f16x2(p0, p1);
    __half2 h2 = *reinterpret_cast<__half2*>(&hi);
    float2 hf = __half22float2(h2);
    lo = cvt_f16x2(p0 - hf.x, p1 - hf.y);
}
// per-element hi|lo pack (V path only)
__device__ __forceinline__ uint32_t pack_f16split(float x) {
    __half h = __float2half_rn(x);
    __half l = __float2half_rn(x - __half2float(h));
    return ((uint32_t)__half_as_ushort(h) << 16) | (uint32_t)__half_as_ushort(l);
}

// ---------------- GEMM: A hi plane, B hi+lo planes --------------------------
// smem u32 layout: As[2][128*20], Bh[2][128*20], Bl[2][128*20]
#define ASTR 20
#define ABUF 2560                 // 128*20
#define GSM_TOTAL (6 * ABUF * 4)  // 61440 B

__global__ __launch_bounds__(256) void gemm_f16_kernel(
    const uint32_t* __restrict__ Ah, const uint32_t* __restrict__ Bh_,
    const uint32_t* __restrict__ Bl_,
    float* __restrict__ Of, uint32_t* __restrict__ Ohi, uint32_t* __restrict__ Olo,
    uint32_t* __restrict__ Opk, const float* __restrict__ bias, int mode)
{
    uint32_t* sm = (uint32_t*)dynsm;
    const uint32_t sbase = smem_u32(sm);

    const int tid = threadIdx.x;
    const int m0 = blockIdx.x * 128;
    const int n0 = blockIdx.y * 128;
    const int lane = tid & 31, wid = tid >> 5;
    const int g = lane >> 2, c = lane & 3;
    const int wm = (wid & 1) * 64;
    const int wn = (wid >> 1) * 32;

    float d[4][4][4];
#pragma unroll
    for (int mt = 0; mt < 4; mt++)
#pragma unroll
        for (int nt = 0; nt < 4; nt++)
#pragma unroll
            for (int i = 0; i < 4; i++) d[mt][nt][i] = 0.f;

    auto load_tile = [&](int t, int buf) {
        const int kp0 = t * 16;
#pragma unroll
        for (int i = 0; i < 2; i++) {
            const int cid = tid + i * 256;            // 0..511
            const int row = cid >> 2, ch = (cid & 3) * 4;
            cpa16(sbase + (buf * ABUF + row * ASTR + ch) * 4,
                  Ah + (size_t)(m0 + row) * DD2 + kp0 + ch);
        }
#pragma unroll
        for (int i = 0; i < 2; i++) {
            const int cid = tid + i * 256;
            const int row = cid >> 2, ch = (cid & 3) * 4;
            cpa16(sbase + (2 * ABUF + buf * ABUF + row * ASTR + ch) * 4,
                  Bh_ + (size_t)(n0 + row) * DD2 + kp0 + ch);
            cpa16(sbase + (4 * ABUF + buf * ABUF + row * ASTR + ch) * 4,
                  Bl_ + (size_t)(n0 + row) * DD2 + kp0 + ch);
        }
    };

    load_tile(0, 0);
    CPA_COMMIT();

    const int NT = DD / 32;  // 32
    for (int t = 0; t < NT; t++) {
        const int buf = t & 1;
        if (t + 1 < NT) {
            load_tile(t + 1, (t + 1) & 1);
            CPA_COMMIT();
            CPA_WAIT1();
        } else {
            CPA_WAIT0();
        }
        __syncthreads();

        const uint32_t* as  = sm + buf * ABUF;
        const uint32_t* bhp = sm + 2 * ABUF + buf * ABUF;
        const uint32_t* blp = sm + 4 * ABUF + buf * ABUF;
#pragma unroll
        for (int kk2 = 0; kk2 < 16; kk2 += 8) {
            uint32_t ah[4][4], bh[4][2], bl[4][2];
#pragma unroll
            for (int mt = 0; mt < 4; mt++) {
                const int rb = wm + mt * 16 + g;
                ah[mt][0] = as[rb * ASTR + kk2 + c];
                ah[mt][1] = as[(rb + 8) * ASTR + kk2 + c];
                ah[mt][2] = as[rb * ASTR + kk2 + c + 4];
                ah[mt][3] = as[(rb + 8) * ASTR + kk2 + c + 4];
            }
#pragma unroll
            for (int nt = 0; nt < 4; nt++) {
                const int nb = wn + nt * 8 + g;
                bh[nt][0] = bhp[nb * ASTR + kk2 + c];
                bh[nt][1] = bhp[nb * ASTR + kk2 + c + 4];
                bl[nt][0] = blp[nb * ASTR + kk2 + c];
                bl[nt][1] = blp[nb * ASTR + kk2 + c + 4];
            }
#pragma unroll
            for (int mt = 0; mt < 4; mt++)
#pragma unroll
                for (int nt = 0; nt < 4; nt++)
                    MMA_F16(d[mt][nt], ah[mt], bl[nt]);
#pragma unroll
            for (int mt = 0; mt < 4; mt++)
#pragma unroll
                for (int nt = 0; nt < 4; nt++)
                    MMA_F16(d[mt][nt], ah[mt], bh[nt]);
        }
        __syncthreads();
    }

#pragma unroll
    for (int mt = 0; mt < 4; mt++) {
        const int r1 = m0 + wm + mt * 16 + g;
        const int r2 = r1 + 8;
#pragma unroll
        for (int nt = 0; nt < 4; nt++) {
            const int cg = n0 + wn + nt * 8 + c * 2;
            if (mode == 0) {
                // Q/K planes: [b,h,s,dpair]
                const int h = cg >> 6, hn2 = (cg & 63) >> 1;
                const int b1 = r1 >> 11, s1 = r1 & (SS - 1);
                const int b2 = r2 >> 11, s2 = r2 & (SS - 1);
                size_t i1 = (((size_t)(b1 * HH + h) * SS + s1) * HD2 + hn2);
                size_t i2 = (((size_t)(b2 * HH + h) * SS + s2) * HD2 + hn2);
                uint32_t h1, l1, h2v, l2;
                psplit(d[mt][nt][0], d[mt][nt][1], h1, l1);
                psplit(d[mt][nt][2], d[mt][nt][3], h2v, l2);
                Ohi[i1] = h1; Olo[i1] = l1;
                Ohi[i2] = h2v; Olo[i2] = l2;
            } else if (mode == 2) {
                // V old packed format
                const int h = cg >> 6, hn = cg & 63;
                const int b1 = r1 >> 11, s1 = r1 & (SS - 1);
                const int b2 = r2 >> 11, s2 = r2 & (SS - 1);
                uint32_t* p1 = Opk + (((size_t)(b1 * HH + h) * SS + s1) * HD + hn);
                uint32_t* p2 = Opk + (((size_t)(b2 * HH + h) * SS + s2) * HD + hn);
                *(uint2*)p1 = make_uint2(pack_f16split(d[mt][nt][0]),
                                         pack_f16split(d[mt][nt][1]));
                *(uint2*)p2 = make_uint2(pack_f16split(d[mt][nt][2]),
                                         pack_f16split(d[mt][nt][3]));
            } else {
                float2 bb = *(const float2*)(bias + cg);
                *(float2*)(Of + (size_t)r1 * DD + cg) =
                    make_float2(d[mt][nt][0] + bb.x, d[mt][nt][1] + bb.y);
                *(float2*)(Of + (size_t)r2 * DD + cg) =
                    make_float2(d[mt][nt][2] + bb.x, d[mt][nt][3] + bb.y);
            }
        }
    }
}

// ---------------- prepass kernels -------------------------------------------
// inputs: f32 -> hi-only f16x2 k-pair plane
__global__ void pack_hi_kernel(const float* __restrict__ in, uint32_t* __restrict__ out) {
    int i = (blockIdx.x * 256 + threadIdx.x) * 4;   // word index
    float4 a = *(const float4*)(in + 2 * i);
    float4 b = *(const float4*)(in + 2 * i + 4);
    uint4 r;
    r.x = cvt_f16x2(a.x, a.y);
    r.y = cvt_f16x2(a.z, a.w);
    r.z = cvt_f16x2(b.x, b.y);
    r.w = cvt_f16x2(b.z, b.w);
    *(uint4*)(out + i) = r;
}

// W [16,1024,64] -> planes [h*64+n][k/2]
__global__ void wtrans_kernel(const float* __restrict__ W,
                              uint32_t* __restrict__ Whi, uint32_t* __restrict__ Wlo) {
    __shared__ float t[32][33];
    const int h = blockIdx.z, k0 = blockIdx.x * 32, n0 = blockIdx.y * 32;
    const int tx = threadIdx.x, ty = threadIdx.y;
#pragma unroll
    for (int i = ty; i < 32; i += 8)
        t[i][tx] = W[((size_t)h * DD + k0 + i) * HD + n0 + tx];
    __syncthreads();
    if (tx < 16) {
#pragma unroll
        for (int i = ty; i < 32; i += 8) {
            uint32_t hi, lo;
            psplit(t[2 * tx][i], t[2 * tx + 1][i], hi, lo);
            size_t idx = (size_t)(h * HD + n0 + i) * DD2 + (k0 >> 1) + tx;
            Whi[idx] = hi;
            Wlo[idx] = lo;
        }
    }
}

// Wo [n][k] -> planes [n][k/2]
__global__ void wo_kernel(const float* __restrict__ Wo,
                          uint32_t* __restrict__ Whi, uint32_t* __restrict__ Wlo) {
    int i = blockIdx.x * 256 + threadIdx.x;
    float2 v = *(const float2*)(Wo + 2 * i);
    uint32_t hi, lo;
    psplit(v.x, v.y, hi, lo);
    Whi[i] = hi;
    Wlo[i] = lo;
}

// ---------------- tensor-core causal flash attention ------------------------
// smem u32: Khi[2][64*36], Klo[2][64*36], V[2][64*68]
#define KSTR 36
#define KBUF 2304                     // 64*36
#define VSTR 68
#define VBUF 4352                     // 64*68
#define FSM_TOTAL ((4 * KBUF + 2 * VBUF) * 4)   // 71680 B

__global__ __launch_bounds__(256) void flash_mma_kernel(
    const uint32_t* __restrict__ Qhi, const uint32_t* __restrict__ Qlo,
    const uint32_t* __restrict__ Khi, const uint32_t* __restrict__ Klo,
    const uint32_t* __restrict__ Vp, uint32_t* __restrict__ AOhi)
{
    uint32_t* sm = (uint32_t*)dynsm;
    const uint32_t sbase = smem_u32(sm);

    const int qi  = (int)gridDim.x - 1 - (int)blockIdx.x;
    const int bh  = blockIdx.y;
    const int b   = bh >> 4, h = bh & 15;
    const int qm0 = qi * 128;

    const uint32_t* Khg = Khi + (size_t)bh * SS * HD2;
    const uint32_t* Klg = Klo + (size_t)bh * SS * HD2;
    const uint32_t* Vh  = Vp  + (size_t)bh * SS * HD;

    const int tid = threadIdx.x;
    const int lane = tid & 31, wid = tid >> 5;
    const int g = lane >> 2, c = lane & 3;
    const int wm = wid * 16;

    // Q fragments from gmem planes
    uint32_t qh[4][4], ql[4][4];
    {
        const uint32_t* q0h = Qhi + ((size_t)bh * SS + qm0 + wm + g) * HD2;
        const uint32_t* q0l = Qlo + ((size_t)bh * SS + qm0 + wm + g) * HD2;
#pragma unroll
        for (int kx = 0; kx < 4; kx++) {
            const int kp = kx * 8 + c;
            qh[kx][0] = q0h[kp];
            qh[kx][1] = q0h[8 * HD2 + kp];
            qh[kx][2] = q0h[kp + 4];
            qh[kx][3] = q0h[8 * HD2 + kp + 4];
            ql[kx][0] = q0l[kp];
            ql[kx][1] = q0l[8 * HD2 + kp];
            ql[kx][2] = q0l[kp + 4];
            ql[kx][3] = q0l[8 * HD2 + kp + 4];
        }
    }

    float m0r = -1e30f, m1r = -1e30f, l0 = 0.f, l1 = 0.f;
    float o[8][4];
#pragma unroll
    for (int j = 0; j < 8; j++)
#pragma unroll
        for (int i = 0; i < 4; i++) o[j][i] = 0.f;

    auto load_kv = [&](int kt, int buf) {
        const uint32_t* khg = Khg + (size_t)kt * 64 * HD2;
        const uint32_t* klg = Klg + (size_t)kt * 64 * HD2;
        const uint32_t* vg  = Vh  + (size_t)kt * 64 * HD;
#pragma unroll
        for (int i = 0; i < 2; i++) {
            const int cid = tid + i * 256;           // 0..511
            const int row = cid >> 3, ch = (cid & 7) * 4;
            cpa16(sbase + (buf * KBUF + row * KSTR + ch) * 4, khg + row * HD2 + ch);
            cpa16(sbase + (2 * KBUF + buf * KBUF + row * KSTR + ch) * 4,
                  klg + row * HD2 + ch);
        }
#pragma unroll
        for (int i = 0; i < 4; i++) {
            const int cid = tid + i * 256;           // 0..1023
            const int row = cid >> 4, ch = (cid & 15) * 4;
            cpa16(sbase + (4 * KBUF + buf * VBUF + row * VSTR + ch) * 4,
                  vg + row * HD + ch);
        }
    };

    const int nkv = 2 * qi + 2;
    load_kv(0, 0);
    CPA_COMMIT();

    const float SC = 0.18033688f;  // 0.125 * log2(e)

    for (int kt = 0; kt < nkv; kt++) {
        const int buf = kt & 1;
        if (kt + 1 < nkv) {
            load_kv(kt + 1, (kt + 1) & 1);
            CPA_COMMIT();
            CPA_WAIT1();
        } else {
            CPA_WAIT0();
        }
        __syncthreads();

        const uint32_t* khs = sm + buf * KBUF;
        const uint32_t* kls = sm + 2 * KBUF + buf * KBUF;
        const uint32_t* vs  = sm + 4 * KBUF + buf * VBUF;

        // ---- S = Q K^T (3-term) ----
        float s[8][4];
#pragma unroll
        for (int j = 0; j < 8; j++)
#pragma unroll
            for (int i = 0; i < 4; i++) s[j][i] = 0.f;

#pragma unroll
        for (int kx = 0; kx < 4; kx++) {
#pragma unroll
            for (int j = 0; j < 8; j++) {
                const int rb = (8 * j + g) * KSTR + kx * 8 + c;
                uint32_t bhf[2], blf[2];
                bhf[0] = khs[rb];
                bhf[1] = khs[rb + 4];
                blf[0] = kls[rb];
                blf[1] = kls[rb + 4];
                MMA_F16(s[j], qh[kx], blf);
                MMA_F16(s[j], ql[kx], bhf);
                MMA_F16(s[j], qh[kx], bhf);
            }
        }

        if (kt >= nkv - 2) {
            const int row0 = qm0 + wm + g, row1 = row0 + 8;
            const int cb = kt * 64 + 2 * c;
#pragma unroll
            for (int j = 0; j < 8; j++) {
                const int c0 = cb + 8 * j;
                if (c0 > row0)     s[j][0] = -1e30f;
                if (c0 + 1 > row0) s[j][1] = -1e30f;
                if (c0 > row1)     s[j][2] = -1e30f;
                if (c0 + 1 > row1) s[j][3] = -1e30f;
            }
        }

        float mx0 = -1e30f, mx1 = -1e30f;
#pragma unroll
        for (int j = 0; j < 8; j++) {
            mx0 = fmaxf(mx0, fmaxf(s[j][0], s[j][1]));
            mx1 = fmaxf(mx1, fmaxf(s[j][2], s[j][3]));
        }
        mx0 = fmaxf(mx0, __shfl_xor_sync(0xffffffffu, mx0, 1));
        mx0 = fmaxf(mx0, __shfl_xor_sync(0xffffffffu, mx0, 2));
        mx1 = fmaxf(mx1, __shfl_xor_sync(0xffffffffu, mx1, 1));
        mx1 = fmaxf(mx1, __shfl_xor_sync(0xffffffffu, mx1, 2));

        const float mn0 = fmaxf(m0r, mx0), mn1 = fmaxf(m1r, mx1);
        const float al0 = exp2f((m0r - mn0) * SC);
        const float al1 = exp2f((m1r - mn1) * SC);
        m0r = mn0; m1r = mn1;

        float rs0 = 0.f, rs1 = 0.f;
#pragma unroll
        for (int j = 0; j < 8; j++) {
            s[j][0] = exp2f((s[j][0] - mn0) * SC);
            s[j][1] = exp2f((s[j][1] - mn0) * SC);
            s[j][2] = exp2f((s[j][2] - mn1) * SC);
            s[j][3] = exp2f((s[j][3] - mn1) * SC);
            rs0 += s[j][0] + s[j][1];
            rs1 += s[j][2] + s[j][3];
        }
        rs0 += __shfl_xor_sync(0xffffffffu, rs0, 1);
        rs0 += __shfl_xor_sync(0xffffffffu, rs0, 2);
        rs1 += __shfl_xor_sync(0xffffffffu, rs1, 1);
        rs1 += __shfl_xor_sync(0xffffffffu, rs1, 2);
        l0 = l0 * al0 + rs0;
        l1 = l1 * al1 + rs1;
#pragma unroll
        for (int j = 0; j < 8; j++) {
            o[j][0] *= al0; o[j][1] *= al0;
            o[j][2] *= al1; o[j][3] *= al1;
        }

        // ---- O += P V (3-term; V frags via PRMT from packed layout) ----
#pragma unroll
        for (int j2 = 0; j2 < 4; j2++) {
            uint32_t ph[4], pl[4];
            psplit(s[2 * j2][0],     s[2 * j2][1],     ph[0], pl[0]);
            psplit(s[2 * j2][2],     s[2 * j2][3],     ph[1], pl[1]);
            psplit(s[2 * j2 + 1][0], s[2 * j2 + 1][1], ph[2], pl[2]);
            psplit(s[2 * j2 + 1][2], s[2 * j2 + 1][3], ph[3], pl[3]);
            const int t0 = 16 * j2 + 2 * c;
#pragma unroll
            for (int jo = 0; jo < 8; jo++) {
                const int dv = 8 * jo + g;
                uint32_t v00 = vs[t0 * VSTR + dv];
                uint32_t v01 = vs[(t0 + 1) * VSTR + dv];
                uint32_t v10 = vs[(t0 + 8) * VSTR + dv];
                uint32_t v11 = vs[(t0 + 9) * VSTR + dv];
                uint32_t bhf[2], blf[2];
                bhf[0] = __byte_perm(v00, v01, 0x7632);
                blf[0] = __byte_perm(v00, v01, 0x5410);
                bhf[1] = __byte_perm(v10, v11, 0x7632);
                blf[1] = __byte_perm(v10, v11, 0x5410);
                MMA_F16(o[jo], ph, blf);
                MMA_F16(o[jo], pl, bhf);
                MMA_F16(o[jo], ph, bhf);
            }
        }
        __syncthreads();
    }

    // epilogue: normalize + hi-only plane store
    const float inv0 = 1.f / l0, inv1 = 1.f / l1;
    const int s0 = qm0 + wm + g, s1 = s0 + 8;
    uint32_t* a0 = AOhi + ((size_t)b * SS + s0) * DD2 + h * HD2;
    uint32_t* a1 = AOhi + ((size_t)b * SS + s1) * DD2 + h * HD2;
#pragma unroll
    for (int j = 0; j < 8; j++) {
        a0[4 * j + c] = cvt_f16x2(o[j][0] * inv0, o[j][1] * inv0);
        a1[4 * j + c] = cvt_f16x2(o[j][2] * inv1, o[j][3] * inv1);
    }
}

// ---------------------------------------------------------------------------
extern "C" void kernel_launch(void* const* d_in, const int* in_sizes, int n_in,
                              void* d_out, int out_size) {
    const float* q  = (const float*)d_in[0];
    const float* k  = (const float*)d_in[1];
    const float* v  = (const float*)d_in[2];
    const float* Wq = (const float*)d_in[3];
    const float* Wk = (const float*)d_in[4];
    const float* Wv = (const float*)d_in[5];
    const float* Wo = (const float*)d_in[6];
    const float* bo = (const float*)d_in[7];
    float* out = (float*)d_out;

    uint32_t *Qhi, *Qlo, *Khi, *Klo, *Vp, *AOhi, *Pq, *Pk, *Pv;
    uint32_t *Wqhi, *Wqlo, *Wkhi, *Wklo, *Wvhi, *Wvlo, *Wohi, *Wolo;
    cudaGetSymbolAddress((void**)&Qhi, g_Qhi);
    cudaGetSymbolAddress((void**)&Qlo, g_Qlo);
    cudaGetSymbolAddress((void**)&Khi, g_Khi);
    cudaGetSymbolAddress((void**)&Klo, g_Klo);
    cudaGetSymbolAddress((void**)&Vp, g_Vp);
    cudaGetSymbolAddress((void**)&AOhi, g_AOhi);
    cudaGetSymbolAddress((void**)&Pq, g_Pq);
    cudaGetSymbolAddress((void**)&Pk, g_Pk);
    cudaGetSymbolAddress((void**)&Pv, g_Pv);
    cudaGetSymbolAddress((void**)&Wqhi, g_Wqhi);
    cudaGetSymbolAddress((void**)&Wqlo, g_Wqlo);
    cudaGetSymbolAddress((void**)&Wkhi, g_Wkhi);
    cudaGetSymbolAddress((void**)&Wklo, g_Wklo);
    cudaGetSymbolAddress((void**)&Wvhi, g_Wvhi);
    cudaGetSymbolAddress((void**)&Wvlo, g_Wvlo);
    cudaGetSymbolAddress((void**)&Wohi, g_Wohi);
    cudaGetSymbolAddress((void**)&Wolo, g_Wolo);

    const int M = BB * SS;                   // 8192
    const int NWORDS = M * DD2;              // 4.19M hi-plane words

    pack_hi_kernel<<<NWORDS / 1024, 256>>>(q, Pq);
    pack_hi_kernel<<<NWORDS / 1024, 256>>>(k, Pk);
    pack_hi_kernel<<<NWORDS / 1024, 256>>>(v, Pv);
    wo_kernel<<<DD * DD2 / 256, 256>>>(Wo, Wohi, Wolo);
    dim3 tb(32, 8);
    dim3 tg(DD / 32, HD / 32, HH);
    wtrans_kernel<<<tg, tb>>>(Wq, Wqhi, Wqlo);
    wtrans_kernel<<<tg, tb>>>(Wk, Wkhi, Wklo);
    wtrans_kernel<<<tg, tb>>>(Wv, Wvhi, Wvlo);

    cudaFuncSetAttribute(gemm_f16_kernel,
                         cudaFuncAttributeMaxDynamicSharedMemorySize, GSM_TOTAL);
    cudaFuncSetAttribute(flash_mma_kernel,
                         cudaFuncAttributeMaxDynamicSharedMemorySize, FSM_TOTAL);

    dim3 gg(M / 128, DD / 128);
    gemm_f16_kernel<<<gg, 256, GSM_TOTAL>>>(Pq, Wqhi, Wqlo, nullptr, Qhi, Qlo,
                                            nullptr, bo, 0);
    gemm_f16_kernel<<<gg, 256, GSM_TOTAL>>>(Pk, Wkhi, Wklo, nullptr, Khi, Klo,
                                            nullptr, bo, 0);
    gemm_f16_kernel<<<gg, 256, GSM_TOTAL>>>(Pv, Wvhi, Wvlo, nullptr, nullptr, nullptr,
                                            Vp, bo, 2);

    flash_mma_kernel<<<dim3(SS / 128, BB * HH), 256, FSM_TOTAL>>>(Qhi, Qlo, Khi, Klo,
                                                                  Vp, AOhi);

    gemm_f16_kernel<<<gg, 256, GSM_TOTAL>>>(AOhi, Wohi, Wolo, out, nullptr, nullptr,
                                            nullptr, bo, 1);
}

// round 16
// speedup vs baseline: 5.4813x; 1.1436x over previous
#include <cuda_runtime.h>
#include <cuda_fp16.h>
#include <math.h>
#include <stdint.h>

#define BB 4
#define SS 2048
#define DD 1024
#define DD2 512
#define HH 16
#define HD 64
#define HD2 32

// ---------------- scratch (device globals; no allocations allowed) ----------
__device__ uint32_t g_Qhi[(size_t)BB * HH * SS * HD2];  // f16x2 d-pair planes
__device__ uint32_t g_Qlo[(size_t)BB * HH * SS * HD2];
__device__ uint32_t g_Khi[(size_t)BB * HH * SS * HD2];
__device__ uint32_t g_Klo[(size_t)BB * HH * SS * HD2];
__device__ uint32_t g_Vh[(size_t)BB * HH * SS * HD2];   // V hi plane f16x2 d-pairs
__device__ uint32_t g_AOhi[(size_t)BB * SS * DD2];      // flash out, hi plane
__device__ uint32_t g_Pq[(size_t)BB * SS * DD2];        // input activations, hi plane
__device__ uint32_t g_Pk[(size_t)BB * SS * DD2];
__device__ uint32_t g_Pv[(size_t)BB * SS * DD2];
__device__ uint32_t g_Wqhi[(size_t)DD * DD2], g_Wqlo[(size_t)DD * DD2];
__device__ uint32_t g_Wkhi[(size_t)DD * DD2], g_Wklo[(size_t)DD * DD2];
__device__ uint32_t g_Wvhi[(size_t)DD * DD2], g_Wvlo[(size_t)DD * DD2];
__device__ uint32_t g_Wohi[(size_t)DD * DD2], g_Wolo[(size_t)DD * DD2];

extern __shared__ char dynsm[];

// ---------------- helpers ---------------------------------------------------
__device__ __forceinline__ uint32_t smem_u32(const void* p) {
    uint32_t a;
    asm("{ .reg .u64 t; cvta.to.shared.u64 t, %1; cvt.u32.u64 %0, t; }"
        : "=r"(a) : "l"(p));
    return a;
}
__device__ __forceinline__ void cpa16(uint32_t dst, const void* src) {
    asm volatile("cp.async.cg.shared.global [%0], [%1], 16;" :: "r"(dst), "l"(src));
}
#define CPA_COMMIT() asm volatile("cp.async.commit_group;" ::: "memory")
#define CPA_WAIT1()  asm volatile("cp.async.wait_group 1;" ::: "memory")
#define CPA_WAIT0()  asm volatile("cp.async.wait_group 0;" ::: "memory")

#define MMA_F16(d, a, b)                                                       \
    asm volatile("mma.sync.aligned.m16n8k16.row.col.f32.f16.f16.f32 "          \
        "{%0,%1,%2,%3}, {%4,%5,%6,%7}, {%8,%9}, {%0,%1,%2,%3};"                \
        : "+f"((d)[0]), "+f"((d)[1]), "+f"((d)[2]), "+f"((d)[3])               \
        : "r"((a)[0]), "r"((a)[1]), "r"((a)[2]), "r"((a)[3]),                  \
          "r"((b)[0]), "r"((b)[1]))

#define LDSM4(r0, r1, r2, r3, a)                                               \
    asm volatile("ldmatrix.sync.aligned.m8n8.x4.shared.b16 {%0,%1,%2,%3}, [%4];" \
        : "=r"(r0), "=r"(r1), "=r"(r2), "=r"(r3) : "r"(a))
#define LDSM4T(r0, r1, r2, r3, a)                                              \
    asm volatile("ldmatrix.sync.aligned.m8n8.x4.trans.shared.b16 {%0,%1,%2,%3}, [%4];" \
        : "=r"(r0), "=r"(r1), "=r"(r2), "=r"(r3) : "r"(a))

// packed f16x2: low half = p0
__device__ __forceinline__ uint32_t cvt_f16x2(float p0, float p1) {
    uint32_t r;
    asm("cvt.rn.f16x2.f32 %0, %1, %2;" : "=r"(r) : "f"(p1), "f"(p0));
    return r;
}
// split a pair into hi f16x2 and residual f16x2
__device__ __forceinline__ void psplit(float p0, float p1, uint32_t& hi, uint32_t& lo) {
    hi = cvt_f16x2(p0, p1);
    __half2 h2 = *reinterpret_cast<__half2*>(&hi);
    float2 hf = __half22float2(h2);
    lo = cvt_f16x2(p0 - hf.x, p1 - hf.y);
}

// ---------------- GEMM: A hi plane, B hi+lo planes --------------------------
// smem u32 layout: As[2][128*20], Bh[2][128*20], Bl[2][128*20]
#define ASTR 20
#define ABUF 2560                 // 128*20 words
#define GSM_TOTAL (6 * ABUF * 4)  // 61440 B

__global__ __launch_bounds__(256) void gemm_f16_kernel(
    const uint32_t* __restrict__ Ah, const uint32_t* __restrict__ Bh_,
    const uint32_t* __restrict__ Bl_,
    float* __restrict__ Of, uint32_t* __restrict__ Ohi, uint32_t* __restrict__ Olo,
    uint32_t* __restrict__ Ovh, const float* __restrict__ bias, int mode)
{
    uint32_t* sm = (uint32_t*)dynsm;
    const uint32_t sbase = smem_u32(sm);

    const int tid = threadIdx.x;
    const int m0 = blockIdx.x * 128;
    const int n0 = blockIdx.y * 128;
    const int lane = tid & 31, wid = tid >> 5;
    const int g = lane >> 2, c = lane & 3;
    const int wm = (wid & 1) * 64;
    const int wn = (wid >> 1) * 32;
    const int rr = lane & 7, sub = lane >> 3;

    // ldmatrix per-lane byte offsets within a buffer
    const uint32_t a_lm = ((wm + rr + (sub & 1) * 8) * ASTR + (sub >> 1) * 4) * 4;
    const uint32_t b_lm = ((wn + rr + (sub & 1) * 8) * ASTR + (sub >> 1) * 4) * 4;

    float d[4][4][4];
#pragma unroll
    for (int mt = 0; mt < 4; mt++)
#pragma unroll
        for (int nt = 0; nt < 4; nt++)
#pragma unroll
            for (int i = 0; i < 4; i++) d[mt][nt][i] = 0.f;

    auto load_tile = [&](int t, int buf) {
        const int kp0 = t * 16;
#pragma unroll
        for (int i = 0; i < 2; i++) {
            const int cid = tid + i * 256;
            const int row = cid >> 2, ch = (cid & 3) * 4;
            cpa16(sbase + (buf * ABUF + row * ASTR + ch) * 4,
                  Ah + (size_t)(m0 + row) * DD2 + kp0 + ch);
        }
#pragma unroll
        for (int i = 0; i < 2; i++) {
            const int cid = tid + i * 256;
            const int row = cid >> 2, ch = (cid & 3) * 4;
            cpa16(sbase + (2 * ABUF + buf * ABUF + row * ASTR + ch) * 4,
                  Bh_ + (size_t)(n0 + row) * DD2 + kp0 + ch);
            cpa16(sbase + (4 * ABUF + buf * ABUF + row * ASTR + ch) * 4,
                  Bl_ + (size_t)(n0 + row) * DD2 + kp0 + ch);
        }
    };

    load_tile(0, 0);
    CPA_COMMIT();

    const int NT = DD / 32;  // 32
    for (int t = 0; t < NT; t++) {
        const int buf = t & 1;
        if (t + 1 < NT) {
            load_tile(t + 1, (t + 1) & 1);
            CPA_COMMIT();
            CPA_WAIT1();
        } else {
            CPA_WAIT0();
        }
        __syncthreads();

        const uint32_t abase = sbase + buf * ABUF * 4;
        const uint32_t bhb = sbase + (2 * ABUF + buf * ABUF) * 4;
        const uint32_t blb = sbase + (4 * ABUF + buf * ABUF) * 4;
#pragma unroll
        for (int kk2 = 0; kk2 < 16; kk2 += 8) {
            uint32_t ah[4][4], bh[4][2], bl[4][2];
#pragma unroll
            for (int mt = 0; mt < 4; mt++)
                LDSM4(ah[mt][0], ah[mt][1], ah[mt][2], ah[mt][3],
                      abase + a_lm + (mt * 16 * ASTR + kk2) * 4);
#pragma unroll
            for (int ntp = 0; ntp < 2; ntp++) {
                LDSM4(bh[2 * ntp][0], bh[2 * ntp + 1][0],
                      bh[2 * ntp][1], bh[2 * ntp + 1][1],
                      bhb + b_lm + (ntp * 16 * ASTR + kk2) * 4);
                LDSM4(bl[2 * ntp][0], bl[2 * ntp + 1][0],
                      bl[2 * ntp][1], bl[2 * ntp + 1][1],
                      blb + b_lm + (ntp * 16 * ASTR + kk2) * 4);
            }
#pragma unroll
            for (int mt = 0; mt < 4; mt++)
#pragma unroll
                for (int nt = 0; nt < 4; nt++)
                    MMA_F16(d[mt][nt], ah[mt], bl[nt]);
#pragma unroll
            for (int mt = 0; mt < 4; mt++)
#pragma unroll
                for (int nt = 0; nt < 4; nt++)
                    MMA_F16(d[mt][nt], ah[mt], bh[nt]);
        }
        __syncthreads();
    }

#pragma unroll
    for (int mt = 0; mt < 4; mt++) {
        const int r1 = m0 + wm + mt * 16 + g;
        const int r2 = r1 + 8;
#pragma unroll
        for (int nt = 0; nt < 4; nt++) {
            const int cg = n0 + wn + nt * 8 + c * 2;
            if (mode == 0) {
                // Q/K planes: [b,h,s,dpair]
                const int h = cg >> 6, hn2 = (cg & 63) >> 1;
                const int b1 = r1 >> 11, s1 = r1 & (SS - 1);
                const int b2 = r2 >> 11, s2 = r2 & (SS - 1);
                size_t i1 = (((size_t)(b1 * HH + h) * SS + s1) * HD2 + hn2);
                size_t i2 = (((size_t)(b2 * HH + h) * SS + s2) * HD2 + hn2);
                uint32_t h1, l1, h2v, l2;
                psplit(d[mt][nt][0], d[mt][nt][1], h1, l1);
                psplit(d[mt][nt][2], d[mt][nt][3], h2v, l2);
                Ohi[i1] = h1; Olo[i1] = l1;
                Ohi[i2] = h2v; Olo[i2] = l2;
            } else if (mode == 2) {
                // V hi plane [b,h,s,dpair]
                const int h = cg >> 6, hn2 = (cg & 63) >> 1;
                const int b1 = r1 >> 11, s1 = r1 & (SS - 1);
                const int b2 = r2 >> 11, s2 = r2 & (SS - 1);
                Ovh[(((size_t)(b1 * HH + h) * SS + s1) * HD2 + hn2)] =
                    cvt_f16x2(d[mt][nt][0], d[mt][nt][1]);
                Ovh[(((size_t)(b2 * HH + h) * SS + s2) * HD2 + hn2)] =
                    cvt_f16x2(d[mt][nt][2], d[mt][nt][3]);
            } else {
                float2 bb = *(const float2*)(bias + cg);
                *(float2*)(Of + (size_t)r1 * DD + cg) =
                    make_float2(d[mt][nt][0] + bb.x, d[mt][nt][1] + bb.y);
                *(float2*)(Of + (size_t)r2 * DD + cg) =
                    make_float2(d[mt][nt][2] + bb.x, d[mt][nt][3] + bb.y);
            }
        }
    }
}

// ---------------- prepass kernels -------------------------------------------
__global__ void pack_hi_kernel(const float* __restrict__ in, uint32_t* __restrict__ out) {
    int i = (blockIdx.x * 256 + threadIdx.x) * 4;
    float4 a = *(const float4*)(in + 2 * i);
    float4 b = *(const float4*)(in + 2 * i + 4);
    uint4 r;
    r.x = cvt_f16x2(a.x, a.y);
    r.y = cvt_f16x2(a.z, a.w);
    r.z = cvt_f16x2(b.x, b.y);
    r.w = cvt_f16x2(b.z, b.w);
    *(uint4*)(out + i) = r;
}

__global__ void wtrans_kernel(const float* __restrict__ W,
                              uint32_t* __restrict__ Whi, uint32_t* __restrict__ Wlo) {
    __shared__ float t[32][33];
    const int h = blockIdx.z, k0 = blockIdx.x * 32, n0 = blockIdx.y * 32;
    const int tx = threadIdx.x, ty = threadIdx.y;
#pragma unroll
    for (int i = ty; i < 32; i += 8)
        t[i][tx] = W[((size_t)h * DD + k0 + i) * HD + n0 + tx];
    __syncthreads();
    if (tx < 16) {
#pragma unroll
        for (int i = ty; i < 32; i += 8) {
            uint32_t hi, lo;
            psplit(t[2 * tx][i], t[2 * tx + 1][i], hi, lo);
            size_t idx = (size_t)(h * HD + n0 + i) * DD2 + (k0 >> 1) + tx;
            Whi[idx] = hi;
            Wlo[idx] = lo;
        }
    }
}

__global__ void wo_kernel(const float* __restrict__ Wo,
                          uint32_t* __restrict__ Whi, uint32_t* __restrict__ Wlo) {
    int i = blockIdx.x * 256 + threadIdx.x;
    float2 v = *(const float2*)(Wo + 2 * i);
    uint32_t hi, lo;
    psplit(v.x, v.y, hi, lo);
    Whi[i] = hi;
    Wlo[i] = lo;
}

// ---------------- tensor-core causal flash attention ------------------------
// smem u32: Khi[2][64*36], Klo[2][64*36], Vh[2][64*36] (f16 [64][72])
#define KSTR 36
#define KBUF 2304                     // 64*36 words
#define FSM_TOTAL (6 * KBUF * 4)      // 55296 B

__global__ __launch_bounds__(256) void flash_mma_kernel(
    const uint32_t* __restrict__ Qhi, const uint32_t* __restrict__ Qlo,
    const uint32_t* __restrict__ Khi, const uint32_t* __restrict__ Klo,
    const uint32_t* __restrict__ Vh, uint32_t* __restrict__ AOhi)
{
    uint32_t* sm = (uint32_t*)dynsm;
    const uint32_t sbase = smem_u32(sm);

    const int qi  = (int)gridDim.x - 1 - (int)blockIdx.x;
    const int bh  = blockIdx.y;
    const int b   = bh >> 4, h = bh & 15;
    const int qm0 = qi * 128;

    const uint32_t* Khg = Khi + (size_t)bh * SS * HD2;
    const uint32_t* Klg = Klo + (size_t)bh * SS * HD2;
    const uint32_t* Vhg = Vh  + (size_t)bh * SS * HD2;

    const int tid = threadIdx.x;
    const int lane = tid & 31, wid = tid >> 5;
    const int g = lane >> 2, c = lane & 3;
    const int wm = wid * 16;
    const int rr = lane & 7, sub = lane >> 3;

    // ldmatrix per-lane byte offsets
    const uint32_t k_lm = ((rr + (sub & 1) * 8) * KSTR + (sub >> 1) * 4) * 4;
    const uint32_t v_lm = (rr + (sub & 1) * 8) * 144 + (sub >> 1) * 16;

    // Q fragments from gmem planes
    uint32_t qh[4][4], ql[4][4];
    {
        const uint32_t* q0h = Qhi + ((size_t)bh * SS + qm0 + wm + g) * HD2;
        const uint32_t* q0l = Qlo + ((size_t)bh * SS + qm0 + wm + g) * HD2;
#pragma unroll
        for (int kx = 0; kx < 4; kx++) {
            const int kp = kx * 8 + c;
            qh[kx][0] = q0h[kp];
            qh[kx][1] = q0h[8 * HD2 + kp];
            qh[kx][2] = q0h[kp + 4];
            qh[kx][3] = q0h[8 * HD2 + kp + 4];
            ql[kx][0] = q0l[kp];
            ql[kx][1] = q0l[8 * HD2 + kp];
            ql[kx][2] = q0l[kp + 4];
            ql[kx][3] = q0l[8 * HD2 + kp + 4];
        }
    }

    float m0r = -1e30f, m1r = -1e30f, l0 = 0.f, l1 = 0.f;
    float o[8][4];
#pragma unroll
    for (int j = 0; j < 8; j++)
#pragma unroll
        for (int i = 0; i < 4; i++) o[j][i] = 0.f;

    auto load_kv = [&](int kt, int buf) {
        const uint32_t* khg = Khg + (size_t)kt * 64 * HD2;
        const uint32_t* klg = Klg + (size_t)kt * 64 * HD2;
        const uint32_t* vg  = Vhg + (size_t)kt * 64 * HD2;
#pragma unroll
        for (int i = 0; i < 2; i++) {
            const int cid = tid + i * 256;           // 0..511
            const int row = cid >> 3, ch = (cid & 7) * 4;
            cpa16(sbase + (buf * KBUF + row * KSTR + ch) * 4, khg + row * HD2 + ch);
            cpa16(sbase + (2 * KBUF + buf * KBUF + row * KSTR + ch) * 4,
                  klg + row * HD2 + ch);
            cpa16(sbase + (4 * KBUF + buf * KBUF + row * KSTR + ch) * 4,
                  vg + row * HD2 + ch);
        }
    };

    const int nkv = 2 * qi + 2;
    load_kv(0, 0);
    CPA_COMMIT();

    const float SC = 0.18033688f;  // 0.125 * log2(e)

    for (int kt = 0; kt < nkv; kt++) {
        const int buf = kt & 1;
        if (kt + 1 < nkv) {
            load_kv(kt + 1, (kt + 1) & 1);
            CPA_COMMIT();
            CPA_WAIT1();
        } else {
            CPA_WAIT0();
        }
        __syncthreads();

        const uint32_t khb = sbase + buf * KBUF * 4;
        const uint32_t klb = sbase + (2 * KBUF + buf * KBUF) * 4;
        const uint32_t vb  = sbase + (4 * KBUF + buf * KBUF) * 4;

        // ---- S = Q K^T (3-term) ----
        float s[8][4];
#pragma unroll
        for (int j = 0; j < 8; j++)
#pragma unroll
            for (int i = 0; i < 4; i++) s[j][i] = 0.f;

#pragma unroll
        for (int kx = 0; kx < 4; kx++) {
#pragma unroll
            for (int j2 = 0; j2 < 4; j2++) {
                uint32_t khA[2], khB[2], klA[2], klB[2];
                const uint32_t addr = k_lm + (j2 * 16 * KSTR + kx * 8) * 4;
                LDSM4(khA[0], khB[0], khA[1], khB[1], khb + addr);
                LDSM4(klA[0], klB[0], klA[1], klB[1], klb + addr);
                MMA_F16(s[2 * j2], qh[kx], klA);
                MMA_F16(s[2 * j2], ql[kx], khA);
                MMA_F16(s[2 * j2], qh[kx], khA);
                MMA_F16(s[2 * j2 + 1], qh[kx], klB);
                MMA_F16(s[2 * j2 + 1], ql[kx], khB);
                MMA_F16(s[2 * j2 + 1], qh[kx], khB);
            }
        }

        if (kt >= nkv - 2) {
            const int row0 = qm0 + wm + g, row1 = row0 + 8;
            const int cb = kt * 64 + 2 * c;
#pragma unroll
            for (int j = 0; j < 8; j++) {
                const int c0 = cb + 8 * j;
                if (c0 > row0)     s[j][0] = -1e30f;
                if (c0 + 1 > row0) s[j][1] = -1e30f;
                if (c0 > row1)     s[j][2] = -1e30f;
                if (c0 + 1 > row1) s[j][3] = -1e30f;
            }
        }

        float mx0 = -1e30f, mx1 = -1e30f;
#pragma unroll
        for (int j = 0; j < 8; j++) {
            mx0 = fmaxf(mx0, fmaxf(s[j][0], s[j][1]));
            mx1 = fmaxf(mx1, fmaxf(s[j][2], s[j][3]));
        }
        mx0 = fmaxf(mx0, __shfl_xor_sync(0xffffffffu, mx0, 1));
        mx0 = fmaxf(mx0, __shfl_xor_sync(0xffffffffu, mx0, 2));
        mx1 = fmaxf(mx1, __shfl_xor_sync(0xffffffffu, mx1, 1));
        mx1 = fmaxf(mx1, __shfl_xor_sync(0xffffffffu, mx1, 2));

        const float mn0 = fmaxf(m0r, mx0), mn1 = fmaxf(m1r, mx1);
        const float al0 = exp2f((m0r - mn0) * SC);
        const float al1 = exp2f((m1r - mn1) * SC);
        m0r = mn0; m1r = mn1;

        float rs0 = 0.f, rs1 = 0.f;
#pragma unroll
        for (int j = 0; j < 8; j++) {
            s[j][0] = exp2f((s[j][0] - mn0) * SC);
            s[j][1] = exp2f((s[j][1] - mn0) * SC);
            s[j][2] = exp2f((s[j][2] - mn1) * SC);
            s[j][3] = exp2f((s[j][3] - mn1) * SC);
            rs0 += s[j][0] + s[j][1];
            rs1 += s[j][2] + s[j][3];
        }
        rs0 += __shfl_xor_sync(0xffffffffu, rs0, 1);
        rs0 += __shfl_xor_sync(0xffffffffu, rs0, 2);
        rs1 += __shfl_xor_sync(0xffffffffu, rs1, 1);
        rs1 += __shfl_xor_sync(0xffffffffu, rs1, 2);
        l0 = l0 * al0 + rs0;
        l1 = l1 * al1 + rs1;
#pragma unroll
        for (int j = 0; j < 8; j++) {
            o[j][0] *= al0; o[j][1] *= al0;
            o[j][2] *= al1; o[j][3] *= al1;
        }

        // ---- O += P V (2-term: (ph+pl)*vh; V frags via ldmatrix.trans) ----
#pragma unroll
        for (int j2 = 0; j2 < 4; j2++) {
            uint32_t ph[4], pl[4];
            psplit(s[2 * j2][0],     s[2 * j2][1],     ph[0], pl[0]);
            psplit(s[2 * j2][2],     s[2 * j2][3],     ph[1], pl[1]);
            psplit(s[2 * j2 + 1][0], s[2 * j2 + 1][1], ph[2], pl[2]);
            psplit(s[2 * j2 + 1][2], s[2 * j2 + 1][3], ph[3], pl[3]);
#pragma unroll
            for (int jo2 = 0; jo2 < 4; jo2++) {
                uint32_t vA[2], vB[2];
                LDSM4T(vA[0], vA[1], vB[0], vB[1],
                       vb + v_lm + j2 * 16 * 144 + jo2 * 32);
                MMA_F16(o[2 * jo2],     pl, vA);
                MMA_F16(o[2 * jo2],     ph, vA);
                MMA_F16(o[2 * jo2 + 1], pl, vB);
                MMA_F16(o[2 * jo2 + 1], ph, vB);
            }
        }
        __syncthreads();
    }

    // epilogue: normalize + hi-only plane store
    const float inv0 = 1.f / l0, inv1 = 1.f / l1;
    const int s0 = qm0 + wm + g, s1 = s0 + 8;
    uint32_t* a0 = AOhi + ((size_t)b * SS + s0) * DD2 + h * HD2;
    uint32_t* a1 = AOhi + ((size_t)b * SS + s1) * DD2 + h * HD2;
#pragma unroll
    for (int j = 0; j < 8; j++) {
        a0[4 * j + c] = cvt_f16x2(o[j][0] * inv0, o[j][1] * inv0);
        a1[4 * j + c] = cvt_f16x2(o[j][2] * inv1, o[j][3] * inv1);
    }
}

// ---------------------------------------------------------------------------
extern "C" void kernel_launch(void* const* d_in, const int* in_sizes, int n_in,
                              void* d_out, int out_size) {
    const float* q  = (const float*)d_in[0];
    const float* k  = (const float*)d_in[1];
    const float* v  = (const float*)d_in[2];
    const float* Wq = (const float*)d_in[3];
    const float* Wk = (const float*)d_in[4];
    const float* Wv = (const float*)d_in[5];
    const float* Wo = (const float*)d_in[6];
    const float* bo = (const float*)d_in[7];
    float* out = (float*)d_out;

    uint32_t *Qhi, *Qlo, *Khi, *Klo, *Vhp, *AOhi, *Pq, *Pk, *Pv;
    uint32_t *Wqhi, *Wqlo, *Wkhi, *Wklo, *Wvhi, *Wvlo, *Wohi, *Wolo;
    cudaGetSymbolAddress((void**)&Qhi, g_Qhi);
    cudaGetSymbolAddress((void**)&Qlo, g_Qlo);
    cudaGetSymbolAddress((void**)&Khi, g_Khi);
    cudaGetSymbolAddress((void**)&Klo, g_Klo);
    cudaGetSymbolAddress((void**)&Vhp, g_Vh);
    cudaGetSymbolAddress((void**)&AOhi, g_AOhi);
    cudaGetSymbolAddress((void**)&Pq, g_Pq);
    cudaGetSymbolAddress((void**)&Pk, g_Pk);
    cudaGetSymbolAddress((void**)&Pv, g_Pv);
    cudaGetSymbolAddress((void**)&Wqhi, g_Wqhi);
    cudaGetSymbolAddress((void**)&Wqlo, g_Wqlo);
    cudaGetSymbolAddress((void**)&Wkhi, g_Wkhi);
    cudaGetSymbolAddress((void**)&Wklo, g_Wklo);
    cudaGetSymbolAddress((void**)&Wvhi, g_Wvhi);
    cudaGetSymbolAddress((void**)&Wvlo, g_Wvlo);
    cudaGetSymbolAddress((void**)&Wohi, g_Wohi);
    cudaGetSymbolAddress((void**)&Wolo, g_Wolo);

    const int M = BB * SS;                   // 8192
    const int NWORDS = M * DD2;              // 4.19M hi-plane words

    pack_hi_kernel<<<NWORDS / 1024, 256>>>(q, Pq);
    pack_hi_kernel<<<NWORDS / 1024, 256>>>(k, Pk);
    pack_hi_kernel<<<NWORDS / 1024, 256>>>(v, Pv);
    wo_kernel<<<DD * DD2 / 256, 256>>>(Wo, Wohi, Wolo);
    dim3 tb(32, 8);
    dim3 tg(DD / 32, HD / 32, HH);
    wtrans_kernel<<<tg, tb>>>(Wq, Wqhi, Wqlo);
    wtrans_kernel<<<tg, tb>>>(Wk, Wkhi, Wklo);
    wtrans_kernel<<<tg, tb>>>(Wv, Wvhi, Wvlo);

    cudaFuncSetAttribute(gemm_f16_kernel,
                         cudaFuncAttributeMaxDynamicSharedMemorySize, GSM_TOTAL);
    cudaFuncSetAttribute(flash_mma_kernel,
                         cudaFuncAttributeMaxDynamicSharedMemorySize, FSM_TOTAL);

    dim3 gg(M / 128, DD / 128);
    gemm_f16_kernel<<<gg, 256, GSM_TOTAL>>>(Pq, Wqhi, Wqlo, nullptr, Qhi, Qlo,
                                            nullptr, bo, 0);
    gemm_f16_kernel<<<gg, 256, GSM_TOTAL>>>(Pk, Wkhi, Wklo, nullptr, Khi, Klo,
                                            nullptr, bo, 0);
    gemm_f16_kernel<<<gg, 256, GSM_TOTAL>>>(Pv, Wvhi, Wvlo, nullptr, nullptr, nullptr,
                                            Vhp, bo, 2);

    flash_mma_kernel<<<dim3(SS / 128, BB * HH), 256, FSM_TOTAL>>>(Qhi, Qlo, Khi, Klo,
                                                                  Vhp, AOhi);

    gemm_f16_kernel<<<gg, 256, GSM_TOTAL>>>(AOhi, Wohi, Wolo, out, nullptr, nullptr,
                                            nullptr, bo, 1);
}